// round 9
// baseline (speedup 1.0000x reference)
#include <cuda_runtime.h>
#include <cuda_bf16.h>
#include <cuda_fp16.h>
#include <math.h>
#include <stdint.h>

typedef __half f16;
typedef unsigned long long u64;
typedef unsigned int u32;

#define BBATCH 2
#define TT 1024
#define DD 768
#define HH 12
#define EE 4
#define NN 2048
#define LL 2
#define VV 50257
#define FF 3072
#define QKVW 4608      // K(768) + V(768) + Q(4*768)

// ------------------- scratch (static device arrays) ------------------------
__device__ __align__(16) float g_x[NN * DD];
__device__ __align__(16) f16   g_ln16[NN * DD];
__device__ __align__(16) f16   g_qkv16[NN * QKVW];
__device__ __align__(16) f16   g_ob16[NN * FF];
__device__ __align__(16) f16   g_h116[NN * FF];
__device__ __align__(16) float g_part[3 * NN * DD];
__device__ float g_coef[NN * EE];

// packed transposed+split fp16 weights (hi+lo)
__device__ __align__(16) f16 g_qkvTHi[LL * QKVW * DD];
__device__ __align__(16) f16 g_qkvTLo[LL * QKVW * DD];
__device__ __align__(16) f16 g_oTHi[LL * DD * FF];
__device__ __align__(16) f16 g_oTLo[LL * DD * FF];
__device__ __align__(16) f16 g_fcTHi[LL * FF * DD];
__device__ __align__(16) f16 g_fcTLo[LL * FF * DD];
__device__ __align__(16) f16 g_pjTHi[LL * DD * FF];
__device__ __align__(16) f16 g_pjTLo[LL * DD * FF];
__device__ __align__(16) f16 g_wteH[VV * DD];      // single plane for lm_head

// ------------------- helpers ------------------------------------------------
__device__ __forceinline__ void split2h(float v, f16& h, f16& l) {
    h = __float2half(v);
    l = __float2half(v - __half2float(h));
}
__device__ __forceinline__ float geluf(float x) {
    float inner = 0.7978845608028654f * (x + 0.044715f * x * x * x);
    return 0.5f * x * (1.0f + tanhf(inner));
}
__device__ __forceinline__ u32 smem_u32(const void* p) {
    u32 a;
    asm("{ .reg .u64 t; cvta.to.shared.u64 t, %1; cvt.u32.u64 %0, t; }"
        : "=r"(a) : "l"(p));
    return a;
}

#define CP16(dst, src, n) \
    asm volatile("cp.async.cg.shared.global [%0], [%1], 16, %2;" \
                 :: "r"(dst), "l"(src), "r"(n) : "memory")
#define CP_COMMIT() asm volatile("cp.async.commit_group;" ::: "memory")
#define CP_WAIT2()  asm volatile("cp.async.wait_group 2;" ::: "memory")
#define CP_WAIT1()  asm volatile("cp.async.wait_group 1;" ::: "memory")
#define CP_WAIT0()  asm volatile("cp.async.wait_group 0;" ::: "memory")

__device__ __forceinline__ void ldmx4(u32* r, u32 addr) {
    asm volatile("ldmatrix.sync.aligned.m8n8.x4.shared.b16 {%0,%1,%2,%3}, [%4];"
        : "=r"(r[0]), "=r"(r[1]), "=r"(r[2]), "=r"(r[3]) : "r"(addr));
}
__device__ __forceinline__ void ldmx4t(u32* r, u32 addr) {
    asm volatile("ldmatrix.sync.aligned.m8n8.x4.trans.shared.b16 {%0,%1,%2,%3}, [%4];"
        : "=r"(r[0]), "=r"(r[1]), "=r"(r[2]), "=r"(r[3]) : "r"(addr));
}
__device__ __forceinline__ void mma16816h(float* c, const u32* a, const u32* b) {
    asm volatile("mma.sync.aligned.m16n8k16.row.col.f32.f16.f16.f32 "
        "{%0,%1,%2,%3}, {%4,%5,%6,%7}, {%8,%9}, {%0,%1,%2,%3};"
        : "+f"(c[0]), "+f"(c[1]), "+f"(c[2]), "+f"(c[3])
        : "r"(a[0]), "r"(a[1]), "r"(a[2]), "r"(a[3]), "r"(b[0]), "r"(b[1]));
}
__device__ __forceinline__ u32 pkhf(float a, float b) {
    __half2 h = __floats2half2_rn(a, b);
    return *(u32*)&h;
}

// ------------------- small kernels ------------------------------------------
__global__ void embed_kernel(const int* __restrict__ idx,
                             const float* __restrict__ wte,
                             const float* __restrict__ wpe,
                             float* __restrict__ x) {
    int n = blockIdx.x;
    int t = n % TT;
    int tok = idx[n];
    const float* we = wte + (size_t)tok * DD;
    const float* wp = wpe + (size_t)t * DD;
    float* xr = x + (size_t)n * DD;
    for (int d = threadIdx.x; d < DD; d += blockDim.x)
        xr[d] = we[d] + wp[d];
}

// LN core: given per-thread 3 values, compute mean/rstd (block of 256)
__device__ __forceinline__ void ln_stats3(int tid, float v0, float v1, float v2,
                                          float& mean, float& rstd) {
    __shared__ float red[8];
    float s = v0 + v1 + v2;
    #pragma unroll
    for (int o = 16; o > 0; o >>= 1) s += __shfl_xor_sync(0xffffffffu, s, o);
    if ((tid & 31) == 0) red[tid >> 5] = s;
    __syncthreads();
    float tot = 0.f;
    #pragma unroll
    for (int i = 0; i < 8; i++) tot += red[i];
    mean = tot * (1.0f / DD);
    __syncthreads();
    float c0 = v0 - mean, c1 = v1 - mean, c2 = v2 - mean;
    float sq = c0 * c0 + c1 * c1 + c2 * c2;
    #pragma unroll
    for (int o = 16; o > 0; o >>= 1) sq += __shfl_xor_sync(0xffffffffu, sq, o);
    if ((tid & 31) == 0) red[tid >> 5] = sq;
    __syncthreads();
    float var = 0.f;
    #pragma unroll
    for (int i = 0; i < 8; i++) var += red[i];
    var *= (1.0f / DD);
    rstd = rsqrtf(var + 1e-5f);
}

// LayerNorm -> single fp16 plane
__global__ void ln16_kernel(const float* __restrict__ x,
                            const float* __restrict__ g,
                            const float* __restrict__ b,
                            f16* __restrict__ y) {
    int r = blockIdx.x;
    int tid = threadIdx.x;   // 256
    const float* xr = x + (size_t)r * DD;
    float v0 = xr[tid], v1 = xr[tid + 256], v2 = xr[tid + 512];
    float mean, rstd;
    ln_stats3(tid, v0, v1, v2, mean, rstd);
    size_t base = (size_t)r * DD;
    y[base + tid]       = __float2half((v0 - mean) * rstd * g[tid]       + b[tid]);
    y[base + tid + 256] = __float2half((v1 - mean) * rstd * g[tid + 256] + b[tid + 256]);
    y[base + tid + 512] = __float2half((v2 - mean) * rstd * g[tid + 512] + b[tid + 512]);
}

// Fused: x += p0+p1+p2 (+bias); then LN(x) -> fp16 plane
__global__ void red_ln16(const float* __restrict__ p,
                         const float* __restrict__ bias,
                         float* __restrict__ x,
                         const float* __restrict__ g,
                         const float* __restrict__ b,
                         f16* __restrict__ y) {
    int r = blockIdx.x;
    int tid = threadIdx.x;   // 256
    size_t rb = (size_t)r * DD;
    float v[3];
    #pragma unroll
    for (int i = 0; i < 3; i++) {
        int d = tid + i * 256;
        float s = p[rb + d] + p[(size_t)NN * DD + rb + d]
                + p[2 * (size_t)NN * DD + rb + d];
        if (bias) s += bias[d];
        float nv = x[rb + d] + s;
        x[rb + d] = nv;
        v[i] = nv;
    }
    float mean, rstd;
    ln_stats3(tid, v[0], v[1], v[2], mean, rstd);
    #pragma unroll
    for (int i = 0; i < 3; i++) {
        int d = tid + i * 256;
        y[rb + d] = __float2half((v[i] - mean) * rstd * g[d] + b[d]);
    }
}

__device__ __forceinline__ float softplusf(float x) {
    if (x > 20.f) return x;
    if (x < -20.f) return expf(x);
    return log1pf(expf(x));
}

// Gate: fp32-exact — reads residual x and applies LN inline.
__global__ void gate_kernel(const float* __restrict__ x,
                            const float* __restrict__ lng,
                            const float* __restrict__ lnb,
                            const float* __restrict__ gw,
                            const float* __restrict__ nw,
                            const float* __restrict__ noise,
                            float* __restrict__ coef) {
    int r = blockIdx.x;
    int tid = threadIdx.x; // 128
    const float* xr = x + (size_t)r * DD;
    float v[6];
    #pragma unroll
    for (int i = 0; i < 6; i++) v[i] = xr[tid + i * 128];

    __shared__ float red[4];
    float s = 0.f;
    #pragma unroll
    for (int i = 0; i < 6; i++) s += v[i];
    #pragma unroll
    for (int o = 16; o > 0; o >>= 1) s += __shfl_xor_sync(0xffffffffu, s, o);
    if ((tid & 31) == 0) red[tid >> 5] = s;
    __syncthreads();
    float mean = (red[0] + red[1] + red[2] + red[3]) * (1.0f / DD);
    __syncthreads();
    float sq = 0.f;
    #pragma unroll
    for (int i = 0; i < 6; i++) { float c = v[i] - mean; sq += c * c; }
    #pragma unroll
    for (int o = 16; o > 0; o >>= 1) sq += __shfl_xor_sync(0xffffffffu, sq, o);
    if ((tid & 31) == 0) red[tid >> 5] = sq;
    __syncthreads();
    float rstd = rsqrtf((red[0] + red[1] + red[2] + red[3]) * (1.0f / DD) + 1e-5f);

    float acc[8] = {0.f, 0.f, 0.f, 0.f, 0.f, 0.f, 0.f, 0.f};
    #pragma unroll
    for (int i = 0; i < 6; i++) {
        int d = tid + i * 128;
        float xv = (v[i] - mean) * rstd * lng[d] + lnb[d];
        #pragma unroll
        for (int e = 0; e < EE; e++) {
            acc[e]     += xv * gw[d * EE + e];
            acc[4 + e] += xv * nw[d * EE + e];
        }
    }
    __shared__ float part[8 * 128];
    #pragma unroll
    for (int e = 0; e < 8; e++) part[e * 128 + tid] = acc[e];
    __syncthreads();
    __shared__ float red8[8];
    if (tid < 8) {
        float t = 0.f;
        for (int i = 0; i < 128; i++) t += part[tid * 128 + i];
        red8[tid] = t;
    }
    __syncthreads();
    if (tid == 0) {
        float lg[4];
        #pragma unroll
        for (int e = 0; e < EE; e++)
            lg[e] = red8[e] + noise[(size_t)r * EE + e] * softplusf(red8[4 + e]);
        int i1 = 0;
        #pragma unroll
        for (int e = 1; e < EE; e++) if (lg[e] > lg[i1]) i1 = e;
        int i2 = -1;
        #pragma unroll
        for (int e = 0; e < EE; e++) {
            if (e == i1) continue;
            if (i2 < 0 || lg[e] > lg[i2]) i2 = e;
        }
        float m = lg[i1];
        float e1 = expf(lg[i1] - m), e2 = expf(lg[i2] - m);
        float inv = 1.f / (e1 + e2);
        float c[4] = {0.f, 0.f, 0.f, 0.f};
        c[i1] = e1 * inv;
        c[i2] = e2 * inv;
        #pragma unroll
        for (int e = 0; e < EE; e++) coef[(size_t)r * EE + e] = c[e];
    }
}

// batched transpose fp32 [K,N] -> split fp16 [N, ld]
#define TRMAX 20
struct TrTable {
    const float* src[TRMAX];
    f16* dhi[TRMAX];
    f16* dlo[TRMAX];
    int  srcN[TRMAX];
    int  ld[TRMAX];
};

__global__ void tr_multi(TrTable t) {
    __shared__ float tile[32][33];
    int z = blockIdx.z;
    const float* src = t.src[z];
    f16* dhi = t.dhi[z];
    f16* dlo = t.dlo[z];
    int N = t.srcN[z], ld = t.ld[z];
    int n0 = blockIdx.x * 32, k0 = blockIdx.y * 32;
    int tx = threadIdx.x, ty = threadIdx.y; // 32x8
    #pragma unroll
    for (int i = 0; i < 4; i++)
        tile[ty + 8 * i][tx] = src[(size_t)(k0 + ty + 8 * i) * N + n0 + tx];
    __syncthreads();
    #pragma unroll
    for (int i = 0; i < 4; i++) {
        float v = tile[tx][ty + 8 * i];
        f16 hv, lv; split2h(v, hv, lv);
        size_t o = (size_t)(n0 + ty + 8 * i) * ld + k0 + tx;
        dhi[o] = hv; dlo[o] = lv;
    }
}

// fp32 -> fp16 single plane (wte)
__global__ void conv16(const float* __restrict__ s, f16* __restrict__ d, int n4) {
    int i = blockIdx.x * 256 + threadIdx.x;
    if (i >= n4) return;
    float4 v = ((const float4*)s)[i];
    __half2* D = (__half2*)d;
    D[2 * i]     = __floats2half2_rn(v.x, v.y);
    D[2 * i + 1] = __floats2half2_rn(v.z, v.w);
}

// ------------------- unified fp16 mma GEMM (3-stage pipeline) ----------------
// C[2048, N] = A(f16) x B^T, B = Bh (+ Bl when NPASS==2), [N][Kstride] K-contig.
// blockIdx.z selects K-partition (split-K) of length Kloop.
// EPI 1: gelu(v+bias)->C16   4: v->C16   5: Cf[z-plane]=v   0: Cf=v (guard N)
#define GLDS 40
#define GMAT (128 * GLDS * 2)

template <int EPI, int NPASS>
__global__ __launch_bounds__(256)
void mma_gemm(const f16* __restrict__ A,
              const f16* __restrict__ Bh, const f16* __restrict__ Bl,
              float* __restrict__ Cf, f16* __restrict__ C16,
              const float* __restrict__ bias, int N, int Kloop, int Kstride) {
    constexpr int NMAT = 1 + NPASS;
    constexpr int STG = NMAT * GMAT;
    extern __shared__ char smdyn[];
    const u32 sb = smem_u32(smdyn);
    const int tid = threadIdx.x, wid = tid >> 5, lane = tid & 31;
    const int row0 = blockIdx.x * 128, col0 = blockIdx.y * 128;
    const int kbase = blockIdx.z * Kloop;
    const int warp_m = (wid & 3) * 32, warp_n = (wid >> 2) * 64;

    float c[2][8][4];
    #pragma unroll
    for (int mt = 0; mt < 2; mt++)
        #pragma unroll
        for (int nt = 0; nt < 8; nt++)
            #pragma unroll
            for (int i = 0; i < 4; i++) c[mt][nt][i] = 0.f;

    const int nch = Kloop >> 5;

    auto load_stage = [&](int s, int k0) {
        u32 st = sb + s * STG;
        #pragma unroll
        for (int i = 0; i < 2; i++) {
            int idx = tid + (i << 8);
            int r = idx >> 2, ch = idx & 3;
            u32 doff = (u32)(r * GLDS + ch * 8) * 2;
            size_t ga = (size_t)(row0 + r) * Kstride + kbase + k0 + ch * 8;
            CP16(st + doff, A + ga, 16);
            int gn = col0 + r;
            int pr = (gn < N) ? 16 : 0;
            int gnc = (gn < N) ? gn : 0;
            size_t gb = (size_t)gnc * Kstride + kbase + k0 + ch * 8;
            CP16(st + GMAT + doff, Bh + gb, pr);
            if (NPASS == 2) CP16(st + 2 * GMAT + doff, Bl + gb, pr);
        }
        CP_COMMIT();
    };

    load_stage(0, 0);
    load_stage(1, 32);
    for (int kc = 0; kc < nch; kc++) {
        if (kc + 2 < nch) { load_stage((kc + 2) % 3, (kc + 2) << 5); CP_WAIT2(); }
        else if (kc + 1 < nch) CP_WAIT1();
        else CP_WAIT0();
        __syncthreads();

        u32 st = sb + (kc % 3) * STG;
        #pragma unroll
        for (int ks = 0; ks < 2; ks++) {
            u32 ah[2][4];
            #pragma unroll
            for (int mt = 0; mt < 2; mt++) {
                u32 ro = (u32)(warp_m + mt * 16 + (lane & 15)) * (GLDS * 2)
                       + (u32)(ks * 16 + ((lane >> 4) << 3)) * 2;
                ldmx4(ah[mt], st + ro);
            }
            #pragma unroll
            for (int j = 0; j < 4; j++) {
                u32 bh[4], bl[4];
                u32 ro = (u32)(warp_n + j * 16 + ((lane >> 4) << 3) + (lane & 7)) * (GLDS * 2)
                       + (u32)(ks * 16 + (((lane >> 3) & 1) << 3)) * 2;
                ldmx4(bh, st + GMAT + ro);
                if (NPASS == 2) ldmx4(bl, st + 2 * GMAT + ro);
                #pragma unroll
                for (int mt = 0; mt < 2; mt++) {
                    mma16816h(c[mt][2 * j], ah[mt], bh);
                    if (NPASS == 2) mma16816h(c[mt][2 * j], ah[mt], bl);
                    mma16816h(c[mt][2 * j + 1], ah[mt], bh + 2);
                    if (NPASS == 2) mma16816h(c[mt][2 * j + 1], ah[mt], bl + 2);
                }
            }
        }
        __syncthreads();
    }

    const size_t pplane = (size_t)blockIdx.z * NN * DD;
    #pragma unroll
    for (int mt = 0; mt < 2; mt++) {
        int rb = row0 + warp_m + mt * 16 + (lane >> 2);
        #pragma unroll
        for (int nt = 0; nt < 8; nt++) {
            int cc = col0 + warp_n + nt * 8 + (lane & 3) * 2;
            float* cr = c[mt][nt];
            #pragma unroll
            for (int h = 0; h < 2; h++) {
                int r = rb + h * 8;
                #pragma unroll
                for (int q = 0; q < 2; q++) {
                    int col = cc + q;
                    float v = cr[h * 2 + q];
                    size_t off = (size_t)r * N + col;
                    if (EPI == 0) {
                        if (col < N) Cf[off] = v;
                    } else if (EPI == 1) {
                        C16[off] = __float2half(geluf(v + bias[col]));
                    } else if (EPI == 4) {
                        C16[off] = __float2half(v);
                    } else {  // 5
                        Cf[pplane + off] = v;
                    }
                }
            }
        }
    }
}

// ------------------- fp16 single-pass flash attention (3-stage KV) -----------
#define AST 72
#define AQB (128 * AST * 2)        // 18432 (Q)
#define AKB (64 * AST * 2)         // 9216 (K or V)
#define AKVSTG (2 * AKB)           // 18432 per stage
#define A_SMEM (AQB + 3 * AKVSTG)  // 73728

__global__ __launch_bounds__(256)
void attn_mma(const f16* __restrict__ qkv, const float* __restrict__ coef,
              f16* __restrict__ ob) {
    extern __shared__ char smdyn[];
    const u32 sb = smem_u32(smdyn);
    const int tid = threadIdx.x, wid = tid >> 5, lane = tid & 31;
    const int q0 = blockIdx.x * 128, hh = blockIdx.y;
    const int b = blockIdx.z >> 2, e = blockIdx.z & 3;
    const u32 QH = sb;
    const size_t qcol = 1536 + (size_t)e * DD + (size_t)hh * 64;

    #pragma unroll
    for (int i = 0; i < 4; i++) {
        int idx = tid + (i << 8);
        int r = idx >> 3, ch = idx & 7;
        size_t g = (size_t)(b * TT + q0 + r) * QKVW + qcol + ch * 8;
        CP16(QH + (u32)(r * AST + ch * 8) * 2, qkv + g, 16);
    }
    auto load_kv = [&](int s, int k0t) {
        u32 st = sb + AQB + s * AKVSTG;
        #pragma unroll
        for (int i = 0; i < 4; i++) {
            int idx = tid + (i << 8);
            int mat = idx >> 9;            // 0:K 1:V
            int r = (idx >> 3) & 63, ch = idx & 7;
            size_t g = (size_t)(b * TT + k0t + r) * QKVW + (size_t)mat * DD
                     + hh * 64 + ch * 8;
            CP16(st + mat * AKB + (u32)(r * AST + ch * 8) * 2, qkv + g, 16);
        }
        CP_COMMIT();
    };
    const int nkt = blockIdx.x * 2 + 2;
    load_kv(0, 0);
    load_kv(1, 64);

    float o[8][4];
    #pragma unroll
    for (int nt = 0; nt < 8; nt++)
        #pragma unroll
        for (int i = 0; i < 4; i++) o[nt][i] = 0.f;
    float mrow[2] = {-1e30f, -1e30f}, lrow[2] = {0.f, 0.f};
    u32 qh[4][4];

    const int warp_r0 = q0 + wid * 16;
    const int rowg0 = warp_r0 + (lane >> 2), rowg1 = rowg0 + 8;

    for (int kt = 0; kt < nkt; kt++) {
        const int k0t = kt * 64;
        if (kt + 2 < nkt) { load_kv((kt + 2) % 3, k0t + 128); CP_WAIT2(); }
        else if (kt + 1 < nkt) CP_WAIT1();
        else CP_WAIT0();
        __syncthreads();

        if (kt == 0) {
            #pragma unroll
            for (int ks = 0; ks < 4; ks++) {
                u32 ro = (u32)(wid * 16 + (lane & 15)) * (AST * 2)
                       + (u32)(ks * 16 + ((lane >> 4) << 3)) * 2;
                ldmx4(qh[ks], QH + ro);
            }
        }

        if (k0t <= warp_r0 + 15) {
            const u32 KH = sb + AQB + (kt % 3) * AKVSTG;
            const u32 VH = KH + AKB;

            float s[8][4];
            #pragma unroll
            for (int nt = 0; nt < 8; nt++)
                #pragma unroll
                for (int i = 0; i < 4; i++) s[nt][i] = 0.f;

            #pragma unroll
            for (int ks = 0; ks < 4; ks++) {
                #pragma unroll
                for (int j = 0; j < 4; j++) {
                    u32 bh[4];
                    u32 ro = (u32)(j * 16 + ((lane >> 4) << 3) + (lane & 7)) * (AST * 2)
                           + (u32)(ks * 16 + (((lane >> 3) & 1) << 3)) * 2;
                    ldmx4(bh, KH + ro);
                    mma16816h(s[2 * j],     qh[ks], bh);
                    mma16816h(s[2 * j + 1], qh[ks], bh + 2);
                }
            }

            const bool diag = (k0t + 63 > warp_r0);
            #pragma unroll
            for (int nt = 0; nt < 8; nt++) {
                int cb = k0t + nt * 8 + (lane & 3) * 2;
                #pragma unroll
                for (int q = 0; q < 2; q++) {
                    int col = cb + q;
                    s[nt][q]     = (diag && col > rowg0) ? -1e30f : s[nt][q] * 0.125f;
                    s[nt][2 + q] = (diag && col > rowg1) ? -1e30f : s[nt][2 + q] * 0.125f;
                }
            }

            float ml0 = -1e30f, ml1 = -1e30f;
            #pragma unroll
            for (int nt = 0; nt < 8; nt++) {
                ml0 = fmaxf(ml0, fmaxf(s[nt][0], s[nt][1]));
                ml1 = fmaxf(ml1, fmaxf(s[nt][2], s[nt][3]));
            }
            ml0 = fmaxf(ml0, __shfl_xor_sync(0xffffffffu, ml0, 1));
            ml0 = fmaxf(ml0, __shfl_xor_sync(0xffffffffu, ml0, 2));
            ml1 = fmaxf(ml1, __shfl_xor_sync(0xffffffffu, ml1, 1));
            ml1 = fmaxf(ml1, __shfl_xor_sync(0xffffffffu, ml1, 2));
            float mn0 = fmaxf(mrow[0], ml0), mn1 = fmaxf(mrow[1], ml1);
            float cr0 = __expf(mrow[0] - mn0), cr1 = __expf(mrow[1] - mn1);
            float rs0 = 0.f, rs1 = 0.f;
            #pragma unroll
            for (int nt = 0; nt < 8; nt++) {
                s[nt][0] = __expf(s[nt][0] - mn0); rs0 += s[nt][0];
                s[nt][1] = __expf(s[nt][1] - mn0); rs0 += s[nt][1];
                s[nt][2] = __expf(s[nt][2] - mn1); rs1 += s[nt][2];
                s[nt][3] = __expf(s[nt][3] - mn1); rs1 += s[nt][3];
            }
            rs0 += __shfl_xor_sync(0xffffffffu, rs0, 1);
            rs0 += __shfl_xor_sync(0xffffffffu, rs0, 2);
            rs1 += __shfl_xor_sync(0xffffffffu, rs1, 1);
            rs1 += __shfl_xor_sync(0xffffffffu, rs1, 2);
            lrow[0] = lrow[0] * cr0 + rs0;
            lrow[1] = lrow[1] * cr1 + rs1;
            mrow[0] = mn0; mrow[1] = mn1;
            #pragma unroll
            for (int nt = 0; nt < 8; nt++) {
                o[nt][0] *= cr0; o[nt][1] *= cr0;
                o[nt][2] *= cr1; o[nt][3] *= cr1;
            }

            #pragma unroll
            for (int t = 0; t < 4; t++) {
                u32 a_h[4];
                #pragma unroll
                for (int half = 0; half < 2; half++) {
                    float* sp = s[2 * t + half];
                    a_h[2 * half]     = pkhf(sp[0], sp[1]);
                    a_h[2 * half + 1] = pkhf(sp[2], sp[3]);
                }
                #pragma unroll
                for (int j = 0; j < 4; j++) {
                    u32 vh[4];
                    int m = lane >> 3;
                    u32 rowv = (u32)(t * 16 + ((m & 1) << 3) + (lane & 7));
                    u32 colv = (u32)(j * 16 + ((m >> 1) << 3));
                    ldmx4t(vh, VH + (rowv * AST + colv) * 2);
                    mma16816h(o[2 * j],     a_h, vh);
                    mma16816h(o[2 * j + 1], a_h, vh + 2);
                }
            }
        }
        __syncthreads();
    }

    size_t rg0 = (size_t)b * TT + rowg0, rg1 = (size_t)b * TT + rowg1;
    float inv0 = coef[rg0 * EE + e] / lrow[0];
    float inv1 = coef[rg1 * EE + e] / lrow[1];
    const size_t ocol = (size_t)e * DD + (size_t)hh * 64;
    #pragma unroll
    for (int nt = 0; nt < 8; nt++) {
        int cb = nt * 8 + (lane & 3) * 2;
        #pragma unroll
        for (int q = 0; q < 2; q++) {
            ob[rg0 * FF + ocol + cb + q] = __float2half(o[nt][q] * inv0);
            ob[rg1 * FF + ocol + cb + q] = __float2half(o[nt][2 + q] * inv1);
        }
    }
}

// ------------------- host ----------------------------------------------------
extern "C" void kernel_launch(void* const* d_in, const int* in_sizes, int n_in,
                              void* d_out, int out_size) {
    const int*   idx     = (const int*)  d_in[0];
    const float* wte     = (const float*)d_in[1];
    const float* wpe     = (const float*)d_in[2];
    const float* ln1_g   = (const float*)d_in[3];
    const float* ln1_b   = (const float*)d_in[4];
    const float* ln2_g   = (const float*)d_in[5];
    const float* ln2_b   = (const float*)d_in[6];
    const float* lnf_g   = (const float*)d_in[7];
    const float* lnf_b   = (const float*)d_in[8];
    const float* Wk      = (const float*)d_in[9];
    const float* Wv      = (const float*)d_in[10];
    const float* Wq      = (const float*)d_in[11];
    const float* Wo      = (const float*)d_in[12];
    const float* gate_w  = (const float*)d_in[13];
    const float* noise_w = (const float*)d_in[14];
    const float* fc_w    = (const float*)d_in[15];
    const float* fc_b    = (const float*)d_in[16];
    const float* proj_w  = (const float*)d_in[17];
    const float* proj_b  = (const float*)d_in[18];
    const float* noise   = (const float*)d_in[19];
    float* out = (float*)d_out;

    float *x, *coef, *part;
    f16 *ln16, *qkv16, *ob16, *h116;
    f16 *qkvTH, *qkvTL, *oTH, *oTL, *fcTH, *fcTL, *pjTH, *pjTL, *wteH;
    cudaGetSymbolAddress((void**)&x,     g_x);
    cudaGetSymbolAddress((void**)&coef,  g_coef);
    cudaGetSymbolAddress((void**)&part,  g_part);
    cudaGetSymbolAddress((void**)&ln16,  g_ln16);
    cudaGetSymbolAddress((void**)&qkv16, g_qkv16);
    cudaGetSymbolAddress((void**)&ob16,  g_ob16);
    cudaGetSymbolAddress((void**)&h116,  g_h116);
    cudaGetSymbolAddress((void**)&qkvTH, g_qkvTHi);
    cudaGetSymbolAddress((void**)&qkvTL, g_qkvTLo);
    cudaGetSymbolAddress((void**)&oTH,   g_oTHi);
    cudaGetSymbolAddress((void**)&oTL,   g_oTLo);
    cudaGetSymbolAddress((void**)&fcTH,  g_fcTHi);
    cudaGetSymbolAddress((void**)&fcTL,  g_fcTLo);
    cudaGetSymbolAddress((void**)&pjTH,  g_pjTHi);
    cudaGetSymbolAddress((void**)&pjTL,  g_pjTLo);
    cudaGetSymbolAddress((void**)&wteH,  g_wteH);

    const int SM2 = 3 * 3 * GMAT;   // NPASS=2, 3 stages
    const int SM1 = 3 * 2 * GMAT;   // NPASS=1, 3 stages
    cudaFuncSetAttribute(mma_gemm<4, 2>, cudaFuncAttributeMaxDynamicSharedMemorySize, SM2);
    cudaFuncSetAttribute(mma_gemm<1, 2>, cudaFuncAttributeMaxDynamicSharedMemorySize, SM2);
    cudaFuncSetAttribute(mma_gemm<5, 2>, cudaFuncAttributeMaxDynamicSharedMemorySize, SM2);
    cudaFuncSetAttribute(mma_gemm<0, 1>, cudaFuncAttributeMaxDynamicSharedMemorySize, SM1);
    cudaFuncSetAttribute(attn_mma, cudaFuncAttributeMaxDynamicSharedMemorySize, A_SMEM);

    const size_t DxD = (size_t)DD * DD;

    // ---- build transpose tables ----
    TrTable tDD = {}, tFC = {}, tPJ = {};
    int nDD = 0;
    for (int l = 0; l < LL; l++) {
        tDD.src[nDD] = Wk + l * DxD;
        tDD.dhi[nDD] = qkvTH + ((size_t)l * QKVW + 0) * DD;
        tDD.dlo[nDD] = qkvTL + ((size_t)l * QKVW + 0) * DD;
        tDD.srcN[nDD] = DD; tDD.ld[nDD] = DD; nDD++;
        tDD.src[nDD] = Wv + l * DxD;
        tDD.dhi[nDD] = qkvTH + ((size_t)l * QKVW + DD) * DD;
        tDD.dlo[nDD] = qkvTL + ((size_t)l * QKVW + DD) * DD;
        tDD.srcN[nDD] = DD; tDD.ld[nDD] = DD; nDD++;
        for (int e = 0; e < EE; e++) {
            tDD.src[nDD] = Wq + ((size_t)l * EE + e) * DxD;
            tDD.dhi[nDD] = qkvTH + ((size_t)l * QKVW + 2 * DD + e * DD) * DD;
            tDD.dlo[nDD] = qkvTL + ((size_t)l * QKVW + 2 * DD + e * DD) * DD;
            tDD.srcN[nDD] = DD; tDD.ld[nDD] = DD; nDD++;
            tDD.src[nDD] = Wo + ((size_t)l * EE + e) * DxD;
            tDD.dhi[nDD] = oTH + (size_t)l * DD * FF + e * DD;
            tDD.dlo[nDD] = oTL + (size_t)l * DD * FF + e * DD;
            tDD.srcN[nDD] = DD; tDD.ld[nDD] = FF; nDD++;
        }
    }
    for (int l = 0; l < LL; l++) {
        tFC.src[l] = fc_w + (size_t)l * DD * FF;
        tFC.dhi[l] = fcTH + (size_t)l * FF * DD;
        tFC.dlo[l] = fcTL + (size_t)l * FF * DD;
        tFC.srcN[l] = FF; tFC.ld[l] = DD;
        tPJ.src[l] = proj_w + (size_t)l * FF * DD;
        tPJ.dhi[l] = pjTH + (size_t)l * DD * FF;
        tPJ.dlo[l] = pjTL + (size_t)l * DD * FF;
        tPJ.srcN[l] = DD; tPJ.ld[l] = FF;
    }

    dim3 trb(32, 8);
    tr_multi<<<dim3(DD / 32, DD / 32, nDD), trb>>>(tDD);
    tr_multi<<<dim3(FF / 32, DD / 32, LL), trb>>>(tFC);
    embed_kernel<<<NN, 256>>>(idx, wte, wpe, x);
    tr_multi<<<dim3(DD / 32, FF / 32, LL), trb>>>(tPJ);
    {
        int n4 = VV * DD / 4;
        conv16<<<(n4 + 255) / 256, 256>>>(wte, wteH, n4);
    }

    dim3 gQKV(NN / 128, QKVW / 128);
    dim3 gFC(NN / 128, FF / 128);
    dim3 gSP(NN / 128, DD / 128, 3);
    dim3 gV(NN / 128, (VV + 127) / 128);
    dim3 gA(TT / 128, HH, BBATCH * EE);

    ln16_kernel<<<NN, 256>>>(x, ln1_g, ln1_b, ln16);
    for (int l = 0; l < LL; l++) {
        mma_gemm<4, 2><<<gQKV, 256, SM2>>>(ln16,
            qkvTH + (size_t)l * QKVW * DD, qkvTL + (size_t)l * QKVW * DD,
            nullptr, qkv16, nullptr, QKVW, DD, DD);
        gate_kernel<<<NN, 128>>>(x, ln1_g + l * DD, ln1_b + l * DD,
                                 gate_w + (size_t)l * DD * EE,
                                 noise_w + (size_t)l * DD * EE,
                                 noise + (size_t)l * NN * EE, coef);
        attn_mma<<<gA, 256, A_SMEM>>>(qkv16, coef, ob16);
        mma_gemm<5, 2><<<gSP, 256, SM2>>>(ob16,
            oTH + (size_t)l * DD * FF, oTL + (size_t)l * DD * FF,
            part, nullptr, nullptr, DD, 1024, FF);
        red_ln16<<<NN, 256>>>(part, nullptr, x,
                              ln2_g + l * DD, ln2_b + l * DD, ln16);
        mma_gemm<1, 2><<<gFC, 256, SM2>>>(ln16,
            fcTH + (size_t)l * FF * DD, fcTL + (size_t)l * FF * DD,
            nullptr, h116, fc_b + (size_t)l * FF, FF, DD, DD);
        mma_gemm<5, 2><<<gSP, 256, SM2>>>(h116,
            pjTH + (size_t)l * DD * FF, pjTL + (size_t)l * DD * FF,
            part, nullptr, nullptr, DD, 1024, FF);
        if (l < LL - 1) {
            red_ln16<<<NN, 256>>>(part, proj_b + (size_t)l * DD, x,
                                  ln1_g + (l + 1) * DD, ln1_b + (l + 1) * DD, ln16);
        } else {
            red_ln16<<<NN, 256>>>(part, proj_b + (size_t)l * DD, x,
                                  lnf_g, lnf_b, ln16);
        }
    }

    mma_gemm<0, 1><<<gV, 256, SM1>>>(ln16, wteH, nullptr,
                                     out, nullptr, nullptr, VV, DD, DD);
}

// round 10
// speedup vs baseline: 1.0580x; 1.0580x over previous
#include <cuda_runtime.h>
#include <cuda_bf16.h>
#include <cuda_fp16.h>
#include <math.h>
#include <stdint.h>

typedef __half f16;
typedef unsigned long long u64;
typedef unsigned int u32;

#define BBATCH 2
#define TT 1024
#define DD 768
#define HH 12
#define EE 4
#define NN 2048
#define LL 2
#define VV 50257
#define FF 3072
#define QKVW 4608      // K(768) + V(768) + Q(4*768)

// ------------------- scratch (static device arrays) ------------------------
__device__ __align__(16) float g_x[NN * DD];
__device__ __align__(16) f16   g_ln16[NN * DD];
__device__ __align__(16) f16   g_qkv16[NN * QKVW];
__device__ __align__(16) f16   g_ob16[NN * FF];
__device__ __align__(16) f16   g_h116[NN * FF];
__device__ __align__(16) float g_part[3 * NN * DD];
__device__ float g_coef[NN * EE];

// packed transposed+split fp16 weights (hi+lo)
__device__ __align__(16) f16 g_qkvTHi[LL * QKVW * DD];
__device__ __align__(16) f16 g_qkvTLo[LL * QKVW * DD];
__device__ __align__(16) f16 g_oTHi[LL * DD * FF];
__device__ __align__(16) f16 g_oTLo[LL * DD * FF];
__device__ __align__(16) f16 g_fcTHi[LL * FF * DD];
__device__ __align__(16) f16 g_fcTLo[LL * FF * DD];
__device__ __align__(16) f16 g_pjTHi[LL * DD * FF];
__device__ __align__(16) f16 g_pjTLo[LL * DD * FF];
__device__ __align__(16) f16 g_wteH[VV * DD];      // single plane for lm_head

// ------------------- helpers ------------------------------------------------
__device__ __forceinline__ void split2h(float v, f16& h, f16& l) {
    h = __float2half(v);
    l = __float2half(v - __half2float(h));
}
__device__ __forceinline__ float geluf(float x) {
    float inner = 0.7978845608028654f * (x + 0.044715f * x * x * x);
    return 0.5f * x * (1.0f + tanhf(inner));
}
__device__ __forceinline__ u32 smem_u32(const void* p) {
    u32 a;
    asm("{ .reg .u64 t; cvta.to.shared.u64 t, %1; cvt.u32.u64 %0, t; }"
        : "=r"(a) : "l"(p));
    return a;
}

#define CP16(dst, src, n) \
    asm volatile("cp.async.cg.shared.global [%0], [%1], 16, %2;" \
                 :: "r"(dst), "l"(src), "r"(n) : "memory")
#define CP_COMMIT() asm volatile("cp.async.commit_group;" ::: "memory")
#define CP_WAIT1()  asm volatile("cp.async.wait_group 1;" ::: "memory")
#define CP_WAIT0()  asm volatile("cp.async.wait_group 0;" ::: "memory")

__device__ __forceinline__ void ldmx4(u32* r, u32 addr) {
    asm volatile("ldmatrix.sync.aligned.m8n8.x4.shared.b16 {%0,%1,%2,%3}, [%4];"
        : "=r"(r[0]), "=r"(r[1]), "=r"(r[2]), "=r"(r[3]) : "r"(addr));
}
__device__ __forceinline__ void ldmx4t(u32* r, u32 addr) {
    asm volatile("ldmatrix.sync.aligned.m8n8.x4.trans.shared.b16 {%0,%1,%2,%3}, [%4];"
        : "=r"(r[0]), "=r"(r[1]), "=r"(r[2]), "=r"(r[3]) : "r"(addr));
}
__device__ __forceinline__ void mma16816h(float* c, const u32* a, const u32* b) {
    asm volatile("mma.sync.aligned.m16n8k16.row.col.f32.f16.f16.f32 "
        "{%0,%1,%2,%3}, {%4,%5,%6,%7}, {%8,%9}, {%0,%1,%2,%3};"
        : "+f"(c[0]), "+f"(c[1]), "+f"(c[2]), "+f"(c[3])
        : "r"(a[0]), "r"(a[1]), "r"(a[2]), "r"(a[3]), "r"(b[0]), "r"(b[1]));
}
__device__ __forceinline__ u32 pkhf(float a, float b) {
    __half2 h = __floats2half2_rn(a, b);
    return *(u32*)&h;
}

// ------------------- small kernels ------------------------------------------
__global__ void embed_kernel(const int* __restrict__ idx,
                             const float* __restrict__ wte,
                             const float* __restrict__ wpe,
                             float* __restrict__ x) {
    int n = blockIdx.x;
    int t = n % TT;
    int tok = idx[n];
    const float* we = wte + (size_t)tok * DD;
    const float* wp = wpe + (size_t)t * DD;
    float* xr = x + (size_t)n * DD;
    for (int d = threadIdx.x; d < DD; d += blockDim.x)
        xr[d] = we[d] + wp[d];
}

// LN stats (block of 256, 3 values/thread)
__device__ __forceinline__ void ln_stats3(int tid, float v0, float v1, float v2,
                                          float& mean, float& rstd) {
    __shared__ float red[8];
    float s = v0 + v1 + v2;
    #pragma unroll
    for (int o = 16; o > 0; o >>= 1) s += __shfl_xor_sync(0xffffffffu, s, o);
    if ((tid & 31) == 0) red[tid >> 5] = s;
    __syncthreads();
    float tot = 0.f;
    #pragma unroll
    for (int i = 0; i < 8; i++) tot += red[i];
    mean = tot * (1.0f / DD);
    __syncthreads();
    float c0 = v0 - mean, c1 = v1 - mean, c2 = v2 - mean;
    float sq = c0 * c0 + c1 * c1 + c2 * c2;
    #pragma unroll
    for (int o = 16; o > 0; o >>= 1) sq += __shfl_xor_sync(0xffffffffu, sq, o);
    if ((tid & 31) == 0) red[tid >> 5] = sq;
    __syncthreads();
    float var = 0.f;
    #pragma unroll
    for (int i = 0; i < 8; i++) var += red[i];
    var *= (1.0f / DD);
    rstd = rsqrtf(var + 1e-5f);
}

__device__ __forceinline__ float softplusf(float x) {
    if (x > 20.f) return x;
    if (x < -20.f) return expf(x);
    return log1pf(expf(x));
}

// Gate tail: given 3 fp32 LN outputs per thread (block 256), compute coef[r].
__device__ __forceinline__ void gate_tail(int r, int tid,
                                          float x0, float x1, float x2,
                                          const float* __restrict__ gw,
                                          const float* __restrict__ nw,
                                          const float* __restrict__ noise,
                                          float* __restrict__ coef) {
    __shared__ float part[8 * 256];
    float acc[8] = {0.f, 0.f, 0.f, 0.f, 0.f, 0.f, 0.f, 0.f};
    float xv[3] = {x0, x1, x2};
    #pragma unroll
    for (int i = 0; i < 3; i++) {
        int d = tid + i * 256;
        #pragma unroll
        for (int e = 0; e < EE; e++) {
            acc[e]     += xv[i] * gw[d * EE + e];
            acc[4 + e] += xv[i] * nw[d * EE + e];
        }
    }
    __syncthreads();   // protect shared reuse
    #pragma unroll
    for (int e = 0; e < 8; e++) part[e * 256 + tid] = acc[e];
    __syncthreads();
    __shared__ float red8[8];
    if (tid < 8) {
        float t = 0.f;
        for (int i = 0; i < 256; i++) t += part[tid * 256 + i];
        red8[tid] = t;
    }
    __syncthreads();
    if (tid == 0) {
        float lg[4];
        #pragma unroll
        for (int e = 0; e < EE; e++)
            lg[e] = red8[e] + noise[(size_t)r * EE + e] * softplusf(red8[4 + e]);
        int i1 = 0;
        #pragma unroll
        for (int e = 1; e < EE; e++) if (lg[e] > lg[i1]) i1 = e;
        int i2 = -1;
        #pragma unroll
        for (int e = 0; e < EE; e++) {
            if (e == i1) continue;
            if (i2 < 0 || lg[e] > lg[i2]) i2 = e;
        }
        float m = lg[i1];
        float e1 = expf(lg[i1] - m), e2 = expf(lg[i2] - m);
        float inv = 1.f / (e1 + e2);
        float c[4] = {0.f, 0.f, 0.f, 0.f};
        c[i1] = e1 * inv;
        c[i2] = e2 * inv;
        #pragma unroll
        for (int e = 0; e < EE; e++) coef[(size_t)r * EE + e] = c[e];
    }
}

// LN -> fp16 plane, plus gate coef (layer entry)
__global__ void ln16g_kernel(const float* __restrict__ x,
                             const float* __restrict__ g,
                             const float* __restrict__ b,
                             f16* __restrict__ y,
                             const float* __restrict__ gw,
                             const float* __restrict__ nw,
                             const float* __restrict__ noise,
                             float* __restrict__ coef) {
    int r = blockIdx.x;
    int tid = threadIdx.x;   // 256
    const float* xr = x + (size_t)r * DD;
    float v0 = xr[tid], v1 = xr[tid + 256], v2 = xr[tid + 512];
    float mean, rstd;
    ln_stats3(tid, v0, v1, v2, mean, rstd);
    size_t base = (size_t)r * DD;
    float o0 = (v0 - mean) * rstd * g[tid]       + b[tid];
    float o1 = (v1 - mean) * rstd * g[tid + 256] + b[tid + 256];
    float o2 = (v2 - mean) * rstd * g[tid + 512] + b[tid + 512];
    y[base + tid]       = __float2half(o0);
    y[base + tid + 256] = __float2half(o1);
    y[base + tid + 512] = __float2half(o2);
    gate_tail(r, tid, o0, o1, o2, gw, nw, noise, coef);
}

// Fused: x += Σ parts (+bias); LN(x) -> fp16 plane; optional gate for next layer
__global__ void red_ln16_kernel(const float* __restrict__ p,
                                const float* __restrict__ bias,
                                float* __restrict__ x,
                                const float* __restrict__ g,
                                const float* __restrict__ b,
                                f16* __restrict__ y,
                                const float* __restrict__ gw,   // null = no gate
                                const float* __restrict__ nw,
                                const float* __restrict__ noise,
                                float* __restrict__ coef) {
    int r = blockIdx.x;
    int tid = threadIdx.x;   // 256
    size_t rb = (size_t)r * DD;
    float v[3];
    #pragma unroll
    for (int i = 0; i < 3; i++) {
        int d = tid + i * 256;
        float s = p[rb + d] + p[(size_t)NN * DD + rb + d]
                + p[2 * (size_t)NN * DD + rb + d];
        if (bias) s += bias[d];
        float nv = x[rb + d] + s;
        x[rb + d] = nv;
        v[i] = nv;
    }
    float mean, rstd;
    ln_stats3(tid, v[0], v[1], v[2], mean, rstd);
    float o[3];
    #pragma unroll
    for (int i = 0; i < 3; i++) {
        int d = tid + i * 256;
        o[i] = (v[i] - mean) * rstd * g[d] + b[d];
        y[rb + d] = __float2half(o[i]);
    }
    if (gw) gate_tail(r, tid, o[0], o[1], o[2], gw, nw, noise, coef);
}

// batched transpose fp32 [K,N] -> split fp16 [N, ld]
#define TRMAX 20
struct TrTable {
    const float* src[TRMAX];
    f16* dhi[TRMAX];
    f16* dlo[TRMAX];
    int  srcN[TRMAX];
    int  ld[TRMAX];
};

__global__ void tr_multi(TrTable t) {
    __shared__ float tile[32][33];
    int z = blockIdx.z;
    const float* src = t.src[z];
    f16* dhi = t.dhi[z];
    f16* dlo = t.dlo[z];
    int N = t.srcN[z], ld = t.ld[z];
    int n0 = blockIdx.x * 32, k0 = blockIdx.y * 32;
    int tx = threadIdx.x, ty = threadIdx.y; // 32x8
    #pragma unroll
    for (int i = 0; i < 4; i++)
        tile[ty + 8 * i][tx] = src[(size_t)(k0 + ty + 8 * i) * N + n0 + tx];
    __syncthreads();
    #pragma unroll
    for (int i = 0; i < 4; i++) {
        float v = tile[tx][ty + 8 * i];
        f16 hv, lv; split2h(v, hv, lv);
        size_t o = (size_t)(n0 + ty + 8 * i) * ld + k0 + tx;
        dhi[o] = hv; dlo[o] = lv;
    }
}

// fp32 -> fp16 single plane (wte)
__global__ void conv16(const float* __restrict__ s, f16* __restrict__ d, int n4) {
    int i = blockIdx.x * 256 + threadIdx.x;
    if (i >= n4) return;
    float4 v = ((const float4*)s)[i];
    __half2* D = (__half2*)d;
    D[2 * i]     = __floats2half2_rn(v.x, v.y);
    D[2 * i + 1] = __floats2half2_rn(v.z, v.w);
}

// ------------------- unified fp16 mma GEMM (3-stage, 1 barrier/iter) ---------
// C[2048, N] = A(f16) x B^T, B = Bh (+ Bl when NPASS==2), [N][Kstride] K-contig.
// blockIdx.z selects K-partition (split-K) of length Kloop.
// EPI 0: Cf=v (guard N)  1: gelu(v+bias)->C16  4: v->C16  5: Cf[z-plane]=v
#define GLDS 40
#define GMAT (128 * GLDS * 2)

template <int EPI, int NPASS>
__global__ __launch_bounds__(256)
void mma_gemm(const f16* __restrict__ A,
              const f16* __restrict__ Bh, const f16* __restrict__ Bl,
              float* __restrict__ Cf, f16* __restrict__ C16,
              const float* __restrict__ bias, int N, int Kloop, int Kstride) {
    constexpr int NMAT = 1 + NPASS;
    constexpr int STG = NMAT * GMAT;
    extern __shared__ char smdyn[];
    const u32 sb = smem_u32(smdyn);
    const int tid = threadIdx.x, wid = tid >> 5, lane = tid & 31;
    const int row0 = blockIdx.x * 128, col0 = blockIdx.y * 128;
    const int kbase = blockIdx.z * Kloop;
    const int warp_m = (wid & 3) * 32, warp_n = (wid >> 2) * 64;

    float c[2][8][4];
    #pragma unroll
    for (int mt = 0; mt < 2; mt++)
        #pragma unroll
        for (int nt = 0; nt < 8; nt++)
            #pragma unroll
            for (int i = 0; i < 4; i++) c[mt][nt][i] = 0.f;

    const int nch = Kloop >> 5;

    auto load_stage = [&](int s, int k0) {
        u32 st = sb + s * STG;
        #pragma unroll
        for (int i = 0; i < 2; i++) {
            int idx = tid + (i << 8);
            int r = idx >> 2, ch = idx & 3;
            u32 doff = (u32)(r * GLDS + ch * 8) * 2;
            size_t ga = (size_t)(row0 + r) * Kstride + kbase + k0 + ch * 8;
            CP16(st + doff, A + ga, 16);
            int gn = col0 + r;
            int pr = (gn < N) ? 16 : 0;
            int gnc = (gn < N) ? gn : 0;
            size_t gb = (size_t)gnc * Kstride + kbase + k0 + ch * 8;
            CP16(st + GMAT + doff, Bh + gb, pr);
            if (NPASS == 2) CP16(st + 2 * GMAT + doff, Bl + gb, pr);
        }
        CP_COMMIT();
    };

    load_stage(0, 0);
    if (nch > 1) load_stage(1, 32);
    for (int kc = 0; kc < nch; kc++) {
        if (kc + 1 < nch) CP_WAIT1();
        else CP_WAIT0();
        __syncthreads();   // all threads' group kc visible; compute kc-1 done
        if (kc + 2 < nch) load_stage((kc + 2) % 3, (kc + 2) << 5);

        u32 st = sb + (kc % 3) * STG;
        #pragma unroll
        for (int ks = 0; ks < 2; ks++) {
            u32 ah[2][4];
            #pragma unroll
            for (int mt = 0; mt < 2; mt++) {
                u32 ro = (u32)(warp_m + mt * 16 + (lane & 15)) * (GLDS * 2)
                       + (u32)(ks * 16 + ((lane >> 4) << 3)) * 2;
                ldmx4(ah[mt], st + ro);
            }
            #pragma unroll
            for (int j = 0; j < 4; j++) {
                u32 bh[4], bl[4];
                u32 ro = (u32)(warp_n + j * 16 + ((lane >> 4) << 3) + (lane & 7)) * (GLDS * 2)
                       + (u32)(ks * 16 + (((lane >> 3) & 1) << 3)) * 2;
                ldmx4(bh, st + GMAT + ro);
                if (NPASS == 2) ldmx4(bl, st + 2 * GMAT + ro);
                #pragma unroll
                for (int mt = 0; mt < 2; mt++) {
                    mma16816h(c[mt][2 * j], ah[mt], bh);
                    if (NPASS == 2) mma16816h(c[mt][2 * j], ah[mt], bl);
                    mma16816h(c[mt][2 * j + 1], ah[mt], bh + 2);
                    if (NPASS == 2) mma16816h(c[mt][2 * j + 1], ah[mt], bl + 2);
                }
            }
        }
    }

    const size_t pplane = (size_t)blockIdx.z * NN * DD;
    #pragma unroll
    for (int mt = 0; mt < 2; mt++) {
        int rb = row0 + warp_m + mt * 16 + (lane >> 2);
        #pragma unroll
        for (int nt = 0; nt < 8; nt++) {
            int cc = col0 + warp_n + nt * 8 + (lane & 3) * 2;
            float* cr = c[mt][nt];
            #pragma unroll
            for (int h = 0; h < 2; h++) {
                int r = rb + h * 8;
                #pragma unroll
                for (int q = 0; q < 2; q++) {
                    int col = cc + q;
                    float v = cr[h * 2 + q];
                    size_t off = (size_t)r * N + col;
                    if (EPI == 0) {
                        if (col < N) Cf[off] = v;
                    } else if (EPI == 1) {
                        C16[off] = __float2half(geluf(v + bias[col]));
                    } else if (EPI == 4) {
                        C16[off] = __float2half(v);
                    } else {  // 5
                        Cf[pplane + off] = v;
                    }
                }
            }
        }
    }
}

// ------------------- fp16 single-pass flash attention (3-stage, 1 barrier) ---
#define AST 72
#define AQB (128 * AST * 2)        // 18432 (Q)
#define AKB (64 * AST * 2)         // 9216 (K or V)
#define AKVSTG (2 * AKB)           // 18432 per stage
#define A_SMEM (AQB + 3 * AKVSTG)  // 73728

__global__ __launch_bounds__(256)
void attn_mma(const f16* __restrict__ qkv, const float* __restrict__ coef,
              f16* __restrict__ ob) {
    extern __shared__ char smdyn[];
    const u32 sb = smem_u32(smdyn);
    const int tid = threadIdx.x, wid = tid >> 5, lane = tid & 31;
    const int q0 = blockIdx.x * 128, hh = blockIdx.y;
    const int b = blockIdx.z >> 2, e = blockIdx.z & 3;
    const u32 QH = sb;
    const size_t qcol = 1536 + (size_t)e * DD + (size_t)hh * 64;

    // group 0: Q + KV tile 0
    #pragma unroll
    for (int i = 0; i < 4; i++) {
        int idx = tid + (i << 8);
        int r = idx >> 3, ch = idx & 7;
        size_t g = (size_t)(b * TT + q0 + r) * QKVW + qcol + ch * 8;
        CP16(QH + (u32)(r * AST + ch * 8) * 2, qkv + g, 16);
    }
    auto load_kv = [&](int s, int k0t) {
        u32 st = sb + AQB + s * AKVSTG;
        #pragma unroll
        for (int i = 0; i < 4; i++) {
            int idx = tid + (i << 8);
            int mat = idx >> 9;            // 0:K 1:V
            int r = (idx >> 3) & 63, ch = idx & 7;
            size_t g = (size_t)(b * TT + k0t + r) * QKVW + (size_t)mat * DD
                     + hh * 64 + ch * 8;
            CP16(st + mat * AKB + (u32)(r * AST + ch * 8) * 2, qkv + g, 16);
        }
        CP_COMMIT();
    };
    const int nkt = blockIdx.x * 2 + 2;
    load_kv(0, 0);
    load_kv(1, 64);

    float o[8][4];
    #pragma unroll
    for (int nt = 0; nt < 8; nt++)
        #pragma unroll
        for (int i = 0; i < 4; i++) o[nt][i] = 0.f;
    float mrow[2] = {-1e30f, -1e30f}, lrow[2] = {0.f, 0.f};
    u32 qh[4][4];

    const int warp_r0 = q0 + wid * 16;
    const int rowg0 = warp_r0 + (lane >> 2), rowg1 = rowg0 + 8;

    for (int kt = 0; kt < nkt; kt++) {
        const int k0t = kt * 64;
        if (kt + 1 < nkt) CP_WAIT1();
        else CP_WAIT0();
        __syncthreads();
        if (kt + 2 < nkt) load_kv((kt + 2) % 3, k0t + 128);

        if (kt == 0) {
            #pragma unroll
            for (int ks = 0; ks < 4; ks++) {
                u32 ro = (u32)(wid * 16 + (lane & 15)) * (AST * 2)
                       + (u32)(ks * 16 + ((lane >> 4) << 3)) * 2;
                ldmx4(qh[ks], QH + ro);
            }
        }

        if (k0t <= warp_r0 + 15) {
            const u32 KH = sb + AQB + (kt % 3) * AKVSTG;
            const u32 VH = KH + AKB;

            float s[8][4];
            #pragma unroll
            for (int nt = 0; nt < 8; nt++)
                #pragma unroll
                for (int i = 0; i < 4; i++) s[nt][i] = 0.f;

            #pragma unroll
            for (int ks = 0; ks < 4; ks++) {
                #pragma unroll
                for (int j = 0; j < 4; j++) {
                    u32 bh[4];
                    u32 ro = (u32)(j * 16 + ((lane >> 4) << 3) + (lane & 7)) * (AST * 2)
                           + (u32)(ks * 16 + (((lane >> 3) & 1) << 3)) * 2;
                    ldmx4(bh, KH + ro);
                    mma16816h(s[2 * j],     qh[ks], bh);
                    mma16816h(s[2 * j + 1], qh[ks], bh + 2);
                }
            }

            const bool diag = (k0t + 63 > warp_r0);
            #pragma unroll
            for (int nt = 0; nt < 8; nt++) {
                int cb = k0t + nt * 8 + (lane & 3) * 2;
                #pragma unroll
                for (int q = 0; q < 2; q++) {
                    int col = cb + q;
                    s[nt][q]     = (diag && col > rowg0) ? -1e30f : s[nt][q] * 0.125f;
                    s[nt][2 + q] = (diag && col > rowg1) ? -1e30f : s[nt][2 + q] * 0.125f;
                }
            }

            float ml0 = -1e30f, ml1 = -1e30f;
            #pragma unroll
            for (int nt = 0; nt < 8; nt++) {
                ml0 = fmaxf(ml0, fmaxf(s[nt][0], s[nt][1]));
                ml1 = fmaxf(ml1, fmaxf(s[nt][2], s[nt][3]));
            }
            ml0 = fmaxf(ml0, __shfl_xor_sync(0xffffffffu, ml0, 1));
            ml0 = fmaxf(ml0, __shfl_xor_sync(0xffffffffu, ml0, 2));
            ml1 = fmaxf(ml1, __shfl_xor_sync(0xffffffffu, ml1, 1));
            ml1 = fmaxf(ml1, __shfl_xor_sync(0xffffffffu, ml1, 2));
            float mn0 = fmaxf(mrow[0], ml0), mn1 = fmaxf(mrow[1], ml1);
            float cr0 = __expf(mrow[0] - mn0), cr1 = __expf(mrow[1] - mn1);
            float rs0 = 0.f, rs1 = 0.f;
            #pragma unroll
            for (int nt = 0; nt < 8; nt++) {
                s[nt][0] = __expf(s[nt][0] - mn0); rs0 += s[nt][0];
                s[nt][1] = __expf(s[nt][1] - mn0); rs0 += s[nt][1];
                s[nt][2] = __expf(s[nt][2] - mn1); rs1 += s[nt][2];
                s[nt][3] = __expf(s[nt][3] - mn1); rs1 += s[nt][3];
            }
            rs0 += __shfl_xor_sync(0xffffffffu, rs0, 1);
            rs0 += __shfl_xor_sync(0xffffffffu, rs0, 2);
            rs1 += __shfl_xor_sync(0xffffffffu, rs1, 1);
            rs1 += __shfl_xor_sync(0xffffffffu, rs1, 2);
            lrow[0] = lrow[0] * cr0 + rs0;
            lrow[1] = lrow[1] * cr1 + rs1;
            mrow[0] = mn0; mrow[1] = mn1;
            #pragma unroll
            for (int nt = 0; nt < 8; nt++) {
                o[nt][0] *= cr0; o[nt][1] *= cr0;
                o[nt][2] *= cr1; o[nt][3] *= cr1;
            }

            #pragma unroll
            for (int t = 0; t < 4; t++) {
                u32 a_h[4];
                #pragma unroll
                for (int half = 0; half < 2; half++) {
                    float* sp = s[2 * t + half];
                    a_h[2 * half]     = pkhf(sp[0], sp[1]);
                    a_h[2 * half + 1] = pkhf(sp[2], sp[3]);
                }
                #pragma unroll
                for (int j = 0; j < 4; j++) {
                    u32 vh[4];
                    int m = lane >> 3;
                    u32 rowv = (u32)(t * 16 + ((m & 1) << 3) + (lane & 7));
                    u32 colv = (u32)(j * 16 + ((m >> 1) << 3));
                    ldmx4t(vh, VH + (rowv * AST + colv) * 2);
                    mma16816h(o[2 * j],     a_h, vh);
                    mma16816h(o[2 * j + 1], a_h, vh + 2);
                }
            }
        }
    }

    size_t rg0 = (size_t)b * TT + rowg0, rg1 = (size_t)b * TT + rowg1;
    float inv0 = coef[rg0 * EE + e] / lrow[0];
    float inv1 = coef[rg1 * EE + e] / lrow[1];
    const size_t ocol = (size_t)e * DD + (size_t)hh * 64;
    #pragma unroll
    for (int nt = 0; nt < 8; nt++) {
        int cb = nt * 8 + (lane & 3) * 2;
        #pragma unroll
        for (int q = 0; q < 2; q++) {
            ob[rg0 * FF + ocol + cb + q] = __float2half(o[nt][q] * inv0);
            ob[rg1 * FF + ocol + cb + q] = __float2half(o[nt][2 + q] * inv1);
        }
    }
}

// ------------------- host ----------------------------------------------------
extern "C" void kernel_launch(void* const* d_in, const int* in_sizes, int n_in,
                              void* d_out, int out_size) {
    const int*   idx     = (const int*)  d_in[0];
    const float* wte     = (const float*)d_in[1];
    const float* wpe     = (const float*)d_in[2];
    const float* ln1_g   = (const float*)d_in[3];
    const float* ln1_b   = (const float*)d_in[4];
    const float* ln2_g   = (const float*)d_in[5];
    const float* ln2_b   = (const float*)d_in[6];
    const float* lnf_g   = (const float*)d_in[7];
    const float* lnf_b   = (const float*)d_in[8];
    const float* Wk      = (const float*)d_in[9];
    const float* Wv      = (const float*)d_in[10];
    const float* Wq      = (const float*)d_in[11];
    const float* Wo      = (const float*)d_in[12];
    const float* gate_w  = (const float*)d_in[13];
    const float* noise_w = (const float*)d_in[14];
    const float* fc_w    = (const float*)d_in[15];
    const float* fc_b    = (const float*)d_in[16];
    const float* proj_w  = (const float*)d_in[17];
    const float* proj_b  = (const float*)d_in[18];
    const float* noise   = (const float*)d_in[19];
    float* out = (float*)d_out;

    float *x, *coef, *part;
    f16 *ln16, *qkv16, *ob16, *h116;
    f16 *qkvTH, *qkvTL, *oTH, *oTL, *fcTH, *fcTL, *pjTH, *pjTL, *wteH;
    cudaGetSymbolAddress((void**)&x,     g_x);
    cudaGetSymbolAddress((void**)&coef,  g_coef);
    cudaGetSymbolAddress((void**)&part,  g_part);
    cudaGetSymbolAddress((void**)&ln16,  g_ln16);
    cudaGetSymbolAddress((void**)&qkv16, g_qkv16);
    cudaGetSymbolAddress((void**)&ob16,  g_ob16);
    cudaGetSymbolAddress((void**)&h116,  g_h116);
    cudaGetSymbolAddress((void**)&qkvTH, g_qkvTHi);
    cudaGetSymbolAddress((void**)&qkvTL, g_qkvTLo);
    cudaGetSymbolAddress((void**)&oTH,   g_oTHi);
    cudaGetSymbolAddress((void**)&oTL,   g_oTLo);
    cudaGetSymbolAddress((void**)&fcTH,  g_fcTHi);
    cudaGetSymbolAddress((void**)&fcTL,  g_fcTLo);
    cudaGetSymbolAddress((void**)&pjTH,  g_pjTHi);
    cudaGetSymbolAddress((void**)&pjTL,  g_pjTLo);
    cudaGetSymbolAddress((void**)&wteH,  g_wteH);

    const int SM2 = 3 * 3 * GMAT;   // NPASS=2, 3 stages = 92160
    const int SM1 = 3 * 2 * GMAT;   // NPASS=1, 3 stages = 61440
    cudaFuncSetAttribute(mma_gemm<4, 2>, cudaFuncAttributeMaxDynamicSharedMemorySize, SM2);
    cudaFuncSetAttribute(mma_gemm<1, 2>, cudaFuncAttributeMaxDynamicSharedMemorySize, SM2);
    cudaFuncSetAttribute(mma_gemm<5, 2>, cudaFuncAttributeMaxDynamicSharedMemorySize, SM2);
    cudaFuncSetAttribute(mma_gemm<0, 1>, cudaFuncAttributeMaxDynamicSharedMemorySize, SM1);
    cudaFuncSetAttribute(attn_mma, cudaFuncAttributeMaxDynamicSharedMemorySize, A_SMEM);

    const size_t DxD = (size_t)DD * DD;

    // ---- build transpose tables ----
    TrTable tDD = {}, tFC = {}, tPJ = {};
    int nDD = 0;
    for (int l = 0; l < LL; l++) {
        tDD.src[nDD] = Wk + l * DxD;
        tDD.dhi[nDD] = qkvTH + ((size_t)l * QKVW + 0) * DD;
        tDD.dlo[nDD] = qkvTL + ((size_t)l * QKVW + 0) * DD;
        tDD.srcN[nDD] = DD; tDD.ld[nDD] = DD; nDD++;
        tDD.src[nDD] = Wv + l * DxD;
        tDD.dhi[nDD] = qkvTH + ((size_t)l * QKVW + DD) * DD;
        tDD.dlo[nDD] = qkvTL + ((size_t)l * QKVW + DD) * DD;
        tDD.srcN[nDD] = DD; tDD.ld[nDD] = DD; nDD++;
        for (int e = 0; e < EE; e++) {
            tDD.src[nDD] = Wq + ((size_t)l * EE + e) * DxD;
            tDD.dhi[nDD] = qkvTH + ((size_t)l * QKVW + 2 * DD + e * DD) * DD;
            tDD.dlo[nDD] = qkvTL + ((size_t)l * QKVW + 2 * DD + e * DD) * DD;
            tDD.srcN[nDD] = DD; tDD.ld[nDD] = DD; nDD++;
            tDD.src[nDD] = Wo + ((size_t)l * EE + e) * DxD;
            tDD.dhi[nDD] = oTH + (size_t)l * DD * FF + e * DD;
            tDD.dlo[nDD] = oTL + (size_t)l * DD * FF + e * DD;
            tDD.srcN[nDD] = DD; tDD.ld[nDD] = FF; nDD++;
        }
    }
    for (int l = 0; l < LL; l++) {
        tFC.src[l] = fc_w + (size_t)l * DD * FF;
        tFC.dhi[l] = fcTH + (size_t)l * FF * DD;
        tFC.dlo[l] = fcTL + (size_t)l * FF * DD;
        tFC.srcN[l] = FF; tFC.ld[l] = DD;
        tPJ.src[l] = proj_w + (size_t)l * FF * DD;
        tPJ.dhi[l] = pjTH + (size_t)l * DD * FF;
        tPJ.dlo[l] = pjTL + (size_t)l * DD * FF;
        tPJ.srcN[l] = DD; tPJ.ld[l] = FF;
    }

    dim3 trb(32, 8);
    // launches 0..4; launch 5 = QKV mma_gemm (ncu -s 5 target)
    tr_multi<<<dim3(DD / 32, DD / 32, nDD), trb>>>(tDD);
    tr_multi<<<dim3(FF / 32, DD / 32, LL), trb>>>(tFC);
    tr_multi<<<dim3(DD / 32, FF / 32, LL), trb>>>(tPJ);
    embed_kernel<<<NN, 256>>>(idx, wte, wpe, x);

    dim3 gQKV(NN / 128, QKVW / 128);
    dim3 gFC(NN / 128, FF / 128);
    dim3 gSP(NN / 128, DD / 128, 3);
    dim3 gV(NN / 128, (VV + 127) / 128);
    dim3 gA(TT / 128, HH, BBATCH * EE);

    ln16g_kernel<<<NN, 256>>>(x, ln1_g, ln1_b, ln16,
                              gate_w, noise_w, noise, coef);
    for (int l = 0; l < LL; l++) {
        mma_gemm<4, 2><<<gQKV, 256, SM2>>>(ln16,
            qkvTH + (size_t)l * QKVW * DD, qkvTL + (size_t)l * QKVW * DD,
            nullptr, qkv16, nullptr, QKVW, DD, DD);
        attn_mma<<<gA, 256, A_SMEM>>>(qkv16, coef, ob16);
        mma_gemm<5, 2><<<gSP, 256, SM2>>>(ob16,
            oTH + (size_t)l * DD * FF, oTL + (size_t)l * DD * FF,
            part, nullptr, nullptr, DD, 1024, FF);
        red_ln16_kernel<<<NN, 256>>>(part, nullptr, x,
            ln2_g + l * DD, ln2_b + l * DD, ln16,
            nullptr, nullptr, nullptr, nullptr);
        mma_gemm<1, 2><<<gFC, 256, SM2>>>(ln16,
            fcTH + (size_t)l * FF * DD, fcTL + (size_t)l * FF * DD,
            nullptr, h116, fc_b + (size_t)l * FF, FF, DD, DD);
        mma_gemm<5, 2><<<gSP, 256, SM2>>>(h116,
            pjTH + (size_t)l * DD * FF, pjTL + (size_t)l * DD * FF,
            part, nullptr, nullptr, DD, 1024, FF);
        if (l < LL - 1) {
            red_ln16_kernel<<<NN, 256>>>(part, proj_b + (size_t)l * DD, x,
                ln1_g + (l + 1) * DD, ln1_b + (l + 1) * DD, ln16,
                gate_w + (size_t)(l + 1) * DD * EE,
                noise_w + (size_t)(l + 1) * DD * EE,
                noise + (size_t)(l + 1) * NN * EE, coef);
        } else {
            red_ln16_kernel<<<NN, 256>>>(part, proj_b + (size_t)l * DD, x,
                lnf_g, lnf_b, ln16,
                nullptr, nullptr, nullptr, nullptr);
        }
    }

    {
        int n4 = VV * DD / 4;
        conv16<<<(n4 + 255) / 256, 256>>>(wte, wteH, n4);
    }
    mma_gemm<0, 1><<<gV, 256, SM1>>>(ln16, wteH, nullptr,
                                     out, nullptr, nullptr, VV, DD, DD);
}

// round 11
// speedup vs baseline: 1.1380x; 1.0755x over previous
#include <cuda_runtime.h>
#include <cuda_bf16.h>
#include <cuda_fp16.h>
#include <math.h>
#include <stdint.h>

typedef __half f16;
typedef unsigned long long u64;
typedef unsigned int u32;

#define BBATCH 2
#define TT 1024
#define DD 768
#define HH 12
#define EE 4
#define NN 2048
#define LL 2
#define VV 50257
#define FF 3072
#define QKVW 4608      // K(768) + V(768) + Q(4*768)

// ------------------- scratch (static device arrays) ------------------------
__device__ __align__(16) float g_x[NN * DD];
__device__ __align__(16) f16   g_ln16[NN * DD];
__device__ __align__(16) f16   g_qkv16[NN * QKVW];
__device__ __align__(16) f16   g_ob16[NN * FF];
__device__ __align__(16) f16   g_h116[NN * FF];
__device__ __align__(16) float g_part[3 * NN * DD];
__device__ float g_coef[NN * EE];

// packed transposed+split fp16 weights (hi+lo)
__device__ __align__(16) f16 g_qkvTHi[LL * QKVW * DD];
__device__ __align__(16) f16 g_qkvTLo[LL * QKVW * DD];
__device__ __align__(16) f16 g_oTHi[LL * DD * FF];
__device__ __align__(16) f16 g_oTLo[LL * DD * FF];
__device__ __align__(16) f16 g_fcTHi[LL * FF * DD];
__device__ __align__(16) f16 g_fcTLo[LL * FF * DD];
__device__ __align__(16) f16 g_pjTHi[LL * DD * FF];
__device__ __align__(16) f16 g_pjTLo[LL * DD * FF];
__device__ __align__(16) f16 g_wteH[VV * DD];      // single plane for lm_head

// ------------------- helpers ------------------------------------------------
__device__ __forceinline__ void split2h(float v, f16& h, f16& l) {
    h = __float2half(v);
    l = __float2half(v - __half2float(h));
}
__device__ __forceinline__ float geluf(float x) {
    float inner = 0.7978845608028654f * (x + 0.044715f * x * x * x);
    return 0.5f * x * (1.0f + tanhf(inner));
}
__device__ __forceinline__ u32 smem_u32(const void* p) {
    u32 a;
    asm("{ .reg .u64 t; cvta.to.shared.u64 t, %1; cvt.u32.u64 %0, t; }"
        : "=r"(a) : "l"(p));
    return a;
}

#define CP16(dst, src, n) \
    asm volatile("cp.async.cg.shared.global [%0], [%1], 16, %2;" \
                 :: "r"(dst), "l"(src), "r"(n) : "memory")
#define CP_COMMIT() asm volatile("cp.async.commit_group;" ::: "memory")
#define CP_WAIT1()  asm volatile("cp.async.wait_group 1;" ::: "memory")
#define CP_WAIT0()  asm volatile("cp.async.wait_group 0;" ::: "memory")

__device__ __forceinline__ void ldmx4(u32* r, u32 addr) {
    asm volatile("ldmatrix.sync.aligned.m8n8.x4.shared.b16 {%0,%1,%2,%3}, [%4];"
        : "=r"(r[0]), "=r"(r[1]), "=r"(r[2]), "=r"(r[3]) : "r"(addr));
}
__device__ __forceinline__ void ldmx4t(u32* r, u32 addr) {
    asm volatile("ldmatrix.sync.aligned.m8n8.x4.trans.shared.b16 {%0,%1,%2,%3}, [%4];"
        : "=r"(r[0]), "=r"(r[1]), "=r"(r[2]), "=r"(r[3]) : "r"(addr));
}
__device__ __forceinline__ void mma16816h(float* c, const u32* a, const u32* b) {
    asm volatile("mma.sync.aligned.m16n8k16.row.col.f32.f16.f16.f32 "
        "{%0,%1,%2,%3}, {%4,%5,%6,%7}, {%8,%9}, {%0,%1,%2,%3};"
        : "+f"(c[0]), "+f"(c[1]), "+f"(c[2]), "+f"(c[3])
        : "r"(a[0]), "r"(a[1]), "r"(a[2]), "r"(a[3]), "r"(b[0]), "r"(b[1]));
}
__device__ __forceinline__ u32 pkhf(float a, float b) {
    __half2 h = __floats2half2_rn(a, b);
    return *(u32*)&h;
}

// ------------------- small kernels ------------------------------------------
__global__ void embed_kernel(const int* __restrict__ idx,
                             const float* __restrict__ wte,
                             const float* __restrict__ wpe,
                             float* __restrict__ x) {
    int n = blockIdx.x;
    int t = n % TT;
    int tok = idx[n];
    const float* we = wte + (size_t)tok * DD;
    const float* wp = wpe + (size_t)t * DD;
    float* xr = x + (size_t)n * DD;
    for (int d = threadIdx.x; d < DD; d += blockDim.x)
        xr[d] = we[d] + wp[d];
}

// LN stats (block of 256, 3 values/thread)
__device__ __forceinline__ void ln_stats3(int tid, float v0, float v1, float v2,
                                          float& mean, float& rstd) {
    __shared__ float red[8];
    float s = v0 + v1 + v2;
    #pragma unroll
    for (int o = 16; o > 0; o >>= 1) s += __shfl_xor_sync(0xffffffffu, s, o);
    if ((tid & 31) == 0) red[tid >> 5] = s;
    __syncthreads();
    float tot = 0.f;
    #pragma unroll
    for (int i = 0; i < 8; i++) tot += red[i];
    mean = tot * (1.0f / DD);
    __syncthreads();
    float c0 = v0 - mean, c1 = v1 - mean, c2 = v2 - mean;
    float sq = c0 * c0 + c1 * c1 + c2 * c2;
    #pragma unroll
    for (int o = 16; o > 0; o >>= 1) sq += __shfl_xor_sync(0xffffffffu, sq, o);
    if ((tid & 31) == 0) red[tid >> 5] = sq;
    __syncthreads();
    float var = 0.f;
    #pragma unroll
    for (int i = 0; i < 8; i++) var += red[i];
    var *= (1.0f / DD);
    rstd = rsqrtf(var + 1e-5f);
}

__device__ __forceinline__ float softplusf(float x) {
    if (x > 20.f) return x;
    if (x < -20.f) return expf(x);
    return log1pf(expf(x));
}

// Gate tail: given 3 fp32 LN outputs per thread (block 256), compute coef[r].
__device__ __forceinline__ void gate_tail(int r, int tid,
                                          float x0, float x1, float x2,
                                          const float* __restrict__ gw,
                                          const float* __restrict__ nw,
                                          const float* __restrict__ noise,
                                          float* __restrict__ coef) {
    __shared__ float part[8 * 256];
    float acc[8] = {0.f, 0.f, 0.f, 0.f, 0.f, 0.f, 0.f, 0.f};
    float xv[3] = {x0, x1, x2};
    #pragma unroll
    for (int i = 0; i < 3; i++) {
        int d = tid + i * 256;
        #pragma unroll
        for (int e = 0; e < EE; e++) {
            acc[e]     += xv[i] * gw[d * EE + e];
            acc[4 + e] += xv[i] * nw[d * EE + e];
        }
    }
    __syncthreads();
    #pragma unroll
    for (int e = 0; e < 8; e++) part[e * 256 + tid] = acc[e];
    __syncthreads();
    __shared__ float red8[8];
    if (tid < 8) {
        float t = 0.f;
        for (int i = 0; i < 256; i++) t += part[tid * 256 + i];
        red8[tid] = t;
    }
    __syncthreads();
    if (tid == 0) {
        float lg[4];
        #pragma unroll
        for (int e = 0; e < EE; e++)
            lg[e] = red8[e] + noise[(size_t)r * EE + e] * softplusf(red8[4 + e]);
        int i1 = 0;
        #pragma unroll
        for (int e = 1; e < EE; e++) if (lg[e] > lg[i1]) i1 = e;
        int i2 = -1;
        #pragma unroll
        for (int e = 0; e < EE; e++) {
            if (e == i1) continue;
            if (i2 < 0 || lg[e] > lg[i2]) i2 = e;
        }
        float m = lg[i1];
        float e1 = expf(lg[i1] - m), e2 = expf(lg[i2] - m);
        float inv = 1.f / (e1 + e2);
        float c[4] = {0.f, 0.f, 0.f, 0.f};
        c[i1] = e1 * inv;
        c[i2] = e2 * inv;
        #pragma unroll
        for (int e = 0; e < EE; e++) coef[(size_t)r * EE + e] = c[e];
    }
}

// LN -> fp16 plane, plus gate coef (layer entry)
__global__ void ln16g_kernel(const float* __restrict__ x,
                             const float* __restrict__ g,
                             const float* __restrict__ b,
                             f16* __restrict__ y,
                             const float* __restrict__ gw,
                             const float* __restrict__ nw,
                             const float* __restrict__ noise,
                             float* __restrict__ coef) {
    int r = blockIdx.x;
    int tid = threadIdx.x;   // 256
    const float* xr = x + (size_t)r * DD;
    float v0 = xr[tid], v1 = xr[tid + 256], v2 = xr[tid + 512];
    float mean, rstd;
    ln_stats3(tid, v0, v1, v2, mean, rstd);
    size_t base = (size_t)r * DD;
    float o0 = (v0 - mean) * rstd * g[tid]       + b[tid];
    float o1 = (v1 - mean) * rstd * g[tid + 256] + b[tid + 256];
    float o2 = (v2 - mean) * rstd * g[tid + 512] + b[tid + 512];
    y[base + tid]       = __float2half(o0);
    y[base + tid + 256] = __float2half(o1);
    y[base + tid + 512] = __float2half(o2);
    gate_tail(r, tid, o0, o1, o2, gw, nw, noise, coef);
}

// Fused: x += Σ parts (+bias); LN(x) -> fp16 plane; optional gate for next layer
__global__ void red_ln16_kernel(const float* __restrict__ p,
                                const float* __restrict__ bias,
                                float* __restrict__ x,
                                const float* __restrict__ g,
                                const float* __restrict__ b,
                                f16* __restrict__ y,
                                const float* __restrict__ gw,   // null = no gate
                                const float* __restrict__ nw,
                                const float* __restrict__ noise,
                                float* __restrict__ coef) {
    int r = blockIdx.x;
    int tid = threadIdx.x;   // 256
    size_t rb = (size_t)r * DD;
    float v[3];
    #pragma unroll
    for (int i = 0; i < 3; i++) {
        int d = tid + i * 256;
        float s = p[rb + d] + p[(size_t)NN * DD + rb + d]
                + p[2 * (size_t)NN * DD + rb + d];
        if (bias) s += bias[d];
        float nv = x[rb + d] + s;
        x[rb + d] = nv;
        v[i] = nv;
    }
    float mean, rstd;
    ln_stats3(tid, v[0], v[1], v[2], mean, rstd);
    float o[3];
    #pragma unroll
    for (int i = 0; i < 3; i++) {
        int d = tid + i * 256;
        o[i] = (v[i] - mean) * rstd * g[d] + b[d];
        y[rb + d] = __float2half(o[i]);
    }
    if (gw) gate_tail(r, tid, o[0], o[1], o[2], gw, nw, noise, coef);
}

// batched transpose fp32 [K,N] -> split fp16 [N, ld]
#define TRMAX 20
struct TrTable {
    const float* src[TRMAX];
    f16* dhi[TRMAX];
    f16* dlo[TRMAX];
    int  srcN[TRMAX];
    int  ld[TRMAX];
};

__global__ void tr_multi(TrTable t) {
    __shared__ float tile[32][33];
    int z = blockIdx.z;
    const float* src = t.src[z];
    f16* dhi = t.dhi[z];
    f16* dlo = t.dlo[z];
    int N = t.srcN[z], ld = t.ld[z];
    int n0 = blockIdx.x * 32, k0 = blockIdx.y * 32;
    int tx = threadIdx.x, ty = threadIdx.y; // 32x8
    #pragma unroll
    for (int i = 0; i < 4; i++)
        tile[ty + 8 * i][tx] = src[(size_t)(k0 + ty + 8 * i) * N + n0 + tx];
    __syncthreads();
    #pragma unroll
    for (int i = 0; i < 4; i++) {
        float v = tile[tx][ty + 8 * i];
        f16 hv, lv; split2h(v, hv, lv);
        size_t o = (size_t)(n0 + ty + 8 * i) * ld + k0 + tx;
        dhi[o] = hv; dlo[o] = lv;
    }
}

// fp32 -> fp16 single plane (wte)
__global__ void conv16(const float* __restrict__ s, f16* __restrict__ d, int n4) {
    int i = blockIdx.x * 256 + threadIdx.x;
    if (i >= n4) return;
    float4 v = ((const float4*)s)[i];
    __half2* D = (__half2*)d;
    D[2 * i]     = __floats2half2_rn(v.x, v.y);
    D[2 * i + 1] = __floats2half2_rn(v.z, v.w);
}

// ------------------- unified fp16 mma GEMM (3-stage, 1 barrier/iter) ---------
// C[2048, N] = A(f16) x B^T, B = Bh (+ Bl when NPASS==2), [N][Kstride] K-contig.
// blockIdx.z selects K-partition (split-K) of length Kloop.
// EPI 0: Cf=v (guard N)  1: gelu(v+bias)->C16  4: v->C16  5: Cf[z-plane]=v
#define GLDS 40
#define GMAT (128 * GLDS * 2)

template <int EPI, int NPASS>
__global__ __launch_bounds__(256)
void mma_gemm(const f16* __restrict__ A,
              const f16* __restrict__ Bh, const f16* __restrict__ Bl,
              float* __restrict__ Cf, f16* __restrict__ C16,
              const float* __restrict__ bias, int N, int Kloop, int Kstride) {
    constexpr int NMAT = 1 + NPASS;
    constexpr int STG = NMAT * GMAT;
    extern __shared__ char smdyn[];
    const u32 sb = smem_u32(smdyn);
    const int tid = threadIdx.x, wid = tid >> 5, lane = tid & 31;
    const int row0 = blockIdx.x * 128, col0 = blockIdx.y * 128;
    const int kbase = blockIdx.z * Kloop;
    const int warp_m = (wid & 3) * 32, warp_n = (wid >> 2) * 64;

    float c[2][8][4];
    #pragma unroll
    for (int mt = 0; mt < 2; mt++)
        #pragma unroll
        for (int nt = 0; nt < 8; nt++)
            #pragma unroll
            for (int i = 0; i < 4; i++) c[mt][nt][i] = 0.f;

    const int nch = Kloop >> 5;

    auto load_stage = [&](int s, int k0) {
        u32 st = sb + s * STG;
        #pragma unroll
        for (int i = 0; i < 2; i++) {
            int idx = tid + (i << 8);
            int r = idx >> 2, ch = idx & 3;
            u32 doff = (u32)(r * GLDS + ch * 8) * 2;
            size_t ga = (size_t)(row0 + r) * Kstride + kbase + k0 + ch * 8;
            CP16(st + doff, A + ga, 16);
            int gn = col0 + r;
            int pr = (gn < N) ? 16 : 0;
            int gnc = (gn < N) ? gn : 0;
            size_t gb = (size_t)gnc * Kstride + kbase + k0 + ch * 8;
            CP16(st + GMAT + doff, Bh + gb, pr);
            if (NPASS == 2) CP16(st + 2 * GMAT + doff, Bl + gb, pr);
        }
        CP_COMMIT();
    };

    load_stage(0, 0);
    if (nch > 1) load_stage(1, 32);
    for (int kc = 0; kc < nch; kc++) {
        if (kc + 1 < nch) CP_WAIT1();
        else CP_WAIT0();
        __syncthreads();   // group kc visible everywhere; compute kc-1 done
        if (kc + 2 < nch) load_stage((kc + 2) % 3, (kc + 2) << 5);

        u32 st = sb + (kc % 3) * STG;
        #pragma unroll
        for (int ks = 0; ks < 2; ks++) {
            u32 ah[2][4];
            #pragma unroll
            for (int mt = 0; mt < 2; mt++) {
                u32 ro = (u32)(warp_m + mt * 16 + (lane & 15)) * (GLDS * 2)
                       + (u32)(ks * 16 + ((lane >> 4) << 3)) * 2;
                ldmx4(ah[mt], st + ro);
            }
            #pragma unroll
            for (int j = 0; j < 4; j++) {
                u32 bh[4], bl[4];
                u32 ro = (u32)(warp_n + j * 16 + ((lane >> 4) << 3) + (lane & 7)) * (GLDS * 2)
                       + (u32)(ks * 16 + (((lane >> 3) & 1) << 3)) * 2;
                ldmx4(bh, st + GMAT + ro);
                if (NPASS == 2) ldmx4(bl, st + 2 * GMAT + ro);
                #pragma unroll
                for (int mt = 0; mt < 2; mt++) {
                    mma16816h(c[mt][2 * j], ah[mt], bh);
                    if (NPASS == 2) mma16816h(c[mt][2 * j], ah[mt], bl);
                    mma16816h(c[mt][2 * j + 1], ah[mt], bh + 2);
                    if (NPASS == 2) mma16816h(c[mt][2 * j + 1], ah[mt], bl + 2);
                }
            }
        }
    }

    const size_t pplane = (size_t)blockIdx.z * NN * DD;
    #pragma unroll
    for (int mt = 0; mt < 2; mt++) {
        int rb = row0 + warp_m + mt * 16 + (lane >> 2);
        #pragma unroll
        for (int nt = 0; nt < 8; nt++) {
            int cc = col0 + warp_n + nt * 8 + (lane & 3) * 2;
            float* cr = c[mt][nt];
            #pragma unroll
            for (int h = 0; h < 2; h++) {
                int r = rb + h * 8;
                #pragma unroll
                for (int q = 0; q < 2; q++) {
                    int col = cc + q;
                    float v = cr[h * 2 + q];
                    size_t off = (size_t)r * N + col;
                    if (EPI == 0) {
                        if (col < N) Cf[off] = v;
                    } else if (EPI == 1) {
                        C16[off] = __float2half(geluf(v + bias[col]));
                    } else if (EPI == 4) {
                        C16[off] = __float2half(v);
                    } else {  // 5
                        Cf[pplane + off] = v;
                    }
                }
            }
        }
    }
}

// ------------------- fp16 single-pass flash attention (3-stage, 1 barrier) ---
// Heaviest q-tiles scheduled first (reversed blockIdx.x) to shrink the tail.
#define AST 72
#define AQB (128 * AST * 2)        // 18432 (Q)
#define AKB (64 * AST * 2)         // 9216 (K or V)
#define AKVSTG (2 * AKB)           // 18432 per stage
#define A_SMEM (AQB + 3 * AKVSTG)  // 73728

__global__ __launch_bounds__(256)
void attn_mma(const f16* __restrict__ qkv, const float* __restrict__ coef,
              f16* __restrict__ ob) {
    extern __shared__ char smdyn[];
    const u32 sb = smem_u32(smdyn);
    const int tid = threadIdx.x, wid = tid >> 5, lane = tid & 31;
    const int qtile = gridDim.x - 1 - blockIdx.x;   // big tiles first
    const int q0 = qtile * 128, hh = blockIdx.y;
    const int b = blockIdx.z >> 2, e = blockIdx.z & 3;
    const u32 QH = sb;
    const size_t qcol = 1536 + (size_t)e * DD + (size_t)hh * 64;

    #pragma unroll
    for (int i = 0; i < 4; i++) {
        int idx = tid + (i << 8);
        int r = idx >> 3, ch = idx & 7;
        size_t g = (size_t)(b * TT + q0 + r) * QKVW + qcol + ch * 8;
        CP16(QH + (u32)(r * AST + ch * 8) * 2, qkv + g, 16);
    }
    auto load_kv = [&](int s, int k0t) {
        u32 st = sb + AQB + s * AKVSTG;
        #pragma unroll
        for (int i = 0; i < 4; i++) {
            int idx = tid + (i << 8);
            int mat = idx >> 9;            // 0:K 1:V
            int r = (idx >> 3) & 63, ch = idx & 7;
            size_t g = (size_t)(b * TT + k0t + r) * QKVW + (size_t)mat * DD
                     + hh * 64 + ch * 8;
            CP16(st + mat * AKB + (u32)(r * AST + ch * 8) * 2, qkv + g, 16);
        }
        CP_COMMIT();
    };
    const int nkt = qtile * 2 + 2;
    load_kv(0, 0);
    load_kv(1, 64);

    float o[8][4];
    #pragma unroll
    for (int nt = 0; nt < 8; nt++)
        #pragma unroll
        for (int i = 0; i < 4; i++) o[nt][i] = 0.f;
    float mrow[2] = {-1e30f, -1e30f}, lrow[2] = {0.f, 0.f};
    u32 qh[4][4];

    const int warp_r0 = q0 + wid * 16;
    const int rowg0 = warp_r0 + (lane >> 2), rowg1 = rowg0 + 8;

    for (int kt = 0; kt < nkt; kt++) {
        const int k0t = kt * 64;
        if (kt + 1 < nkt) CP_WAIT1();
        else CP_WAIT0();
        __syncthreads();
        if (kt + 2 < nkt) load_kv((kt + 2) % 3, k0t + 128);

        if (kt == 0) {
            #pragma unroll
            for (int ks = 0; ks < 4; ks++) {
                u32 ro = (u32)(wid * 16 + (lane & 15)) * (AST * 2)
                       + (u32)(ks * 16 + ((lane >> 4) << 3)) * 2;
                ldmx4(qh[ks], QH + ro);
            }
        }

        if (k0t <= warp_r0 + 15) {
            const u32 KH = sb + AQB + (kt % 3) * AKVSTG;
            const u32 VH = KH + AKB;

            float s[8][4];
            #pragma unroll
            for (int nt = 0; nt < 8; nt++)
                #pragma unroll
                for (int i = 0; i < 4; i++) s[nt][i] = 0.f;

            #pragma unroll
            for (int ks = 0; ks < 4; ks++) {
                #pragma unroll
                for (int j = 0; j < 4; j++) {
                    u32 bh[4];
                    u32 ro = (u32)(j * 16 + ((lane >> 4) << 3) + (lane & 7)) * (AST * 2)
                           + (u32)(ks * 16 + (((lane >> 3) & 1) << 3)) * 2;
                    ldmx4(bh, KH + ro);
                    mma16816h(s[2 * j],     qh[ks], bh);
                    mma16816h(s[2 * j + 1], qh[ks], bh + 2);
                }
            }

            const bool diag = (k0t + 63 > warp_r0);
            #pragma unroll
            for (int nt = 0; nt < 8; nt++) {
                int cb = k0t + nt * 8 + (lane & 3) * 2;
                #pragma unroll
                for (int q = 0; q < 2; q++) {
                    int col = cb + q;
                    s[nt][q]     = (diag && col > rowg0) ? -1e30f : s[nt][q] * 0.125f;
                    s[nt][2 + q] = (diag && col > rowg1) ? -1e30f : s[nt][2 + q] * 0.125f;
                }
            }

            float ml0 = -1e30f, ml1 = -1e30f;
            #pragma unroll
            for (int nt = 0; nt < 8; nt++) {
                ml0 = fmaxf(ml0, fmaxf(s[nt][0], s[nt][1]));
                ml1 = fmaxf(ml1, fmaxf(s[nt][2], s[nt][3]));
            }
            ml0 = fmaxf(ml0, __shfl_xor_sync(0xffffffffu, ml0, 1));
            ml0 = fmaxf(ml0, __shfl_xor_sync(0xffffffffu, ml0, 2));
            ml1 = fmaxf(ml1, __shfl_xor_sync(0xffffffffu, ml1, 1));
            ml1 = fmaxf(ml1, __shfl_xor_sync(0xffffffffu, ml1, 2));
            float mn0 = fmaxf(mrow[0], ml0), mn1 = fmaxf(mrow[1], ml1);
            float cr0 = __expf(mrow[0] - mn0), cr1 = __expf(mrow[1] - mn1);
            float rs0 = 0.f, rs1 = 0.f;
            #pragma unroll
            for (int nt = 0; nt < 8; nt++) {
                s[nt][0] = __expf(s[nt][0] - mn0); rs0 += s[nt][0];
                s[nt][1] = __expf(s[nt][1] - mn0); rs0 += s[nt][1];
                s[nt][2] = __expf(s[nt][2] - mn1); rs1 += s[nt][2];
                s[nt][3] = __expf(s[nt][3] - mn1); rs1 += s[nt][3];
            }
            rs0 += __shfl_xor_sync(0xffffffffu, rs0, 1);
            rs0 += __shfl_xor_sync(0xffffffffu, rs0, 2);
            rs1 += __shfl_xor_sync(0xffffffffu, rs1, 1);
            rs1 += __shfl_xor_sync(0xffffffffu, rs1, 2);
            lrow[0] = lrow[0] * cr0 + rs0;
            lrow[1] = lrow[1] * cr1 + rs1;
            mrow[0] = mn0; mrow[1] = mn1;
            #pragma unroll
            for (int nt = 0; nt < 8; nt++) {
                o[nt][0] *= cr0; o[nt][1] *= cr0;
                o[nt][2] *= cr1; o[nt][3] *= cr1;
            }

            #pragma unroll
            for (int t = 0; t < 4; t++) {
                u32 a_h[4];
                #pragma unroll
                for (int half = 0; half < 2; half++) {
                    float* sp = s[2 * t + half];
                    a_h[2 * half]     = pkhf(sp[0], sp[1]);
                    a_h[2 * half + 1] = pkhf(sp[2], sp[3]);
                }
                #pragma unroll
                for (int j = 0; j < 4; j++) {
                    u32 vh[4];
                    int m = lane >> 3;
                    u32 rowv = (u32)(t * 16 + ((m & 1) << 3) + (lane & 7));
                    u32 colv = (u32)(j * 16 + ((m >> 1) << 3));
                    ldmx4t(vh, VH + (rowv * AST + colv) * 2);
                    mma16816h(o[2 * j],     a_h, vh);
                    mma16816h(o[2 * j + 1], a_h, vh + 2);
                }
            }
        }
    }

    size_t rg0 = (size_t)b * TT + rowg0, rg1 = (size_t)b * TT + rowg1;
    float inv0 = coef[rg0 * EE + e] / lrow[0];
    float inv1 = coef[rg1 * EE + e] / lrow[1];
    const size_t ocol = (size_t)e * DD + (size_t)hh * 64;
    #pragma unroll
    for (int nt = 0; nt < 8; nt++) {
        int cb = nt * 8 + (lane & 3) * 2;
        #pragma unroll
        for (int q = 0; q < 2; q++) {
            ob[rg0 * FF + ocol + cb + q] = __float2half(o[nt][q] * inv0);
            ob[rg1 * FF + ocol + cb + q] = __float2half(o[nt][2 + q] * inv1);
        }
    }
}

// ------------------- host ----------------------------------------------------
extern "C" void kernel_launch(void* const* d_in, const int* in_sizes, int n_in,
                              void* d_out, int out_size) {
    const int*   idx     = (const int*)  d_in[0];
    const float* wte     = (const float*)d_in[1];
    const float* wpe     = (const float*)d_in[2];
    const float* ln1_g   = (const float*)d_in[3];
    const float* ln1_b   = (const float*)d_in[4];
    const float* ln2_g   = (const float*)d_in[5];
    const float* ln2_b   = (const float*)d_in[6];
    const float* lnf_g   = (const float*)d_in[7];
    const float* lnf_b   = (const float*)d_in[8];
    const float* Wk      = (const float*)d_in[9];
    const float* Wv      = (const float*)d_in[10];
    const float* Wq      = (const float*)d_in[11];
    const float* Wo      = (const float*)d_in[12];
    const float* gate_w  = (const float*)d_in[13];
    const float* noise_w = (const float*)d_in[14];
    const float* fc_w    = (const float*)d_in[15];
    const float* fc_b    = (const float*)d_in[16];
    const float* proj_w  = (const float*)d_in[17];
    const float* proj_b  = (const float*)d_in[18];
    const float* noise   = (const float*)d_in[19];
    float* out = (float*)d_out;

    float *x, *coef, *part;
    f16 *ln16, *qkv16, *ob16, *h116;
    f16 *qkvTH, *qkvTL, *oTH, *oTL, *fcTH, *fcTL, *pjTH, *pjTL, *wteH;
    cudaGetSymbolAddress((void**)&x,     g_x);
    cudaGetSymbolAddress((void**)&coef,  g_coef);
    cudaGetSymbolAddress((void**)&part,  g_part);
    cudaGetSymbolAddress((void**)&ln16,  g_ln16);
    cudaGetSymbolAddress((void**)&qkv16, g_qkv16);
    cudaGetSymbolAddress((void**)&ob16,  g_ob16);
    cudaGetSymbolAddress((void**)&h116,  g_h116);
    cudaGetSymbolAddress((void**)&qkvTH, g_qkvTHi);
    cudaGetSymbolAddress((void**)&qkvTL, g_qkvTLo);
    cudaGetSymbolAddress((void**)&oTH,   g_oTHi);
    cudaGetSymbolAddress((void**)&oTL,   g_oTLo);
    cudaGetSymbolAddress((void**)&fcTH,  g_fcTHi);
    cudaGetSymbolAddress((void**)&fcTL,  g_fcTLo);
    cudaGetSymbolAddress((void**)&pjTH,  g_pjTHi);
    cudaGetSymbolAddress((void**)&pjTL,  g_pjTLo);
    cudaGetSymbolAddress((void**)&wteH,  g_wteH);

    const int SM2 = 3 * 3 * GMAT;   // NPASS=2, 3 stages = 92160
    const int SM1 = 3 * 2 * GMAT;   // NPASS=1, 3 stages = 61440
    cudaFuncSetAttribute(mma_gemm<4, 2>, cudaFuncAttributeMaxDynamicSharedMemorySize, SM2);
    cudaFuncSetAttribute(mma_gemm<1, 2>, cudaFuncAttributeMaxDynamicSharedMemorySize, SM2);
    cudaFuncSetAttribute(mma_gemm<5, 1>, cudaFuncAttributeMaxDynamicSharedMemorySize, SM1);
    cudaFuncSetAttribute(mma_gemm<0, 1>, cudaFuncAttributeMaxDynamicSharedMemorySize, SM1);
    cudaFuncSetAttribute(attn_mma, cudaFuncAttributeMaxDynamicSharedMemorySize, A_SMEM);

    const size_t DxD = (size_t)DD * DD;

    // ---- build transpose tables ----
    TrTable tDD = {}, tFC = {}, tPJ = {};
    int nDD = 0;
    for (int l = 0; l < LL; l++) {
        tDD.src[nDD] = Wk + l * DxD;
        tDD.dhi[nDD] = qkvTH + ((size_t)l * QKVW + 0) * DD;
        tDD.dlo[nDD] = qkvTL + ((size_t)l * QKVW + 0) * DD;
        tDD.srcN[nDD] = DD; tDD.ld[nDD] = DD; nDD++;
        tDD.src[nDD] = Wv + l * DxD;
        tDD.dhi[nDD] = qkvTH + ((size_t)l * QKVW + DD) * DD;
        tDD.dlo[nDD] = qkvTL + ((size_t)l * QKVW + DD) * DD;
        tDD.srcN[nDD] = DD; tDD.ld[nDD] = DD; nDD++;
        for (int e = 0; e < EE; e++) {
            tDD.src[nDD] = Wq + ((size_t)l * EE + e) * DxD;
            tDD.dhi[nDD] = qkvTH + ((size_t)l * QKVW + 2 * DD + e * DD) * DD;
            tDD.dlo[nDD] = qkvTL + ((size_t)l * QKVW + 2 * DD + e * DD) * DD;
            tDD.srcN[nDD] = DD; tDD.ld[nDD] = DD; nDD++;
            tDD.src[nDD] = Wo + ((size_t)l * EE + e) * DxD;
            tDD.dhi[nDD] = oTH + (size_t)l * DD * FF + e * DD;
            tDD.dlo[nDD] = oTL + (size_t)l * DD * FF + e * DD;
            tDD.srcN[nDD] = DD; tDD.ld[nDD] = FF; nDD++;
        }
    }
    for (int l = 0; l < LL; l++) {
        tFC.src[l] = fc_w + (size_t)l * DD * FF;
        tFC.dhi[l] = fcTH + (size_t)l * FF * DD;
        tFC.dlo[l] = fcTL + (size_t)l * FF * DD;
        tFC.srcN[l] = FF; tFC.ld[l] = DD;
        tPJ.src[l] = proj_w + (size_t)l * FF * DD;
        tPJ.dhi[l] = pjTH + (size_t)l * DD * FF;
        tPJ.dlo[l] = pjTL + (size_t)l * DD * FF;
        tPJ.srcN[l] = DD; tPJ.ld[l] = FF;
    }

    dim3 trb(32, 8);
    dim3 gQKV(NN / 128, QKVW / 128);
    dim3 gFC(NN / 128, FF / 128);
    dim3 gSP(NN / 128, DD / 128, 3);
    dim3 gV(NN / 128, (VV + 127) / 128);
    dim3 gA(TT / 128, HH, BBATCH * EE);

    // ordering: ours #3 == ncu global #5 (2 harness-internal launches observed)
    embed_kernel<<<NN, 256>>>(idx, wte, wpe, x);                            // 0
    ln16g_kernel<<<NN, 256>>>(x, ln1_g, ln1_b, ln16,
                              gate_w, noise_w, noise, coef);                // 1
    tr_multi<<<dim3(DD / 32, DD / 32, nDD), trb>>>(tDD);                    // 2
    mma_gemm<4, 2><<<gQKV, 256, SM2>>>(ln16, qkvTH, qkvTL,
        nullptr, qkv16, nullptr, QKVW, DD, DD);                             // 3 <- ncu
    tr_multi<<<dim3(FF / 32, DD / 32, LL), trb>>>(tFC);                     // 4
    tr_multi<<<dim3(DD / 32, FF / 32, LL), trb>>>(tPJ);                     // 5

    for (int l = 0; l < LL; l++) {
        if (l > 0) {
            mma_gemm<4, 2><<<gQKV, 256, SM2>>>(ln16,
                qkvTH + (size_t)l * QKVW * DD, qkvTL + (size_t)l * QKVW * DD,
                nullptr, qkv16, nullptr, QKVW, DD, DD);
        }
        attn_mma<<<gA, 256, A_SMEM>>>(qkv16, coef, ob16);
        mma_gemm<5, 1><<<gSP, 256, SM1>>>(ob16,
            oTH + (size_t)l * DD * FF, nullptr,
            part, nullptr, nullptr, DD, 1024, FF);
        red_ln16_kernel<<<NN, 256>>>(part, nullptr, x,
            ln2_g + l * DD, ln2_b + l * DD, ln16,
            nullptr, nullptr, nullptr, nullptr);
        mma_gemm<1, 2><<<gFC, 256, SM2>>>(ln16,
            fcTH + (size_t)l * FF * DD, fcTL + (size_t)l * FF * DD,
            nullptr, h116, fc_b + (size_t)l * FF, FF, DD, DD);
        mma_gemm<5, 1><<<gSP, 256, SM1>>>(h116,
            pjTH + (size_t)l * DD * FF, nullptr,
            part, nullptr, nullptr, DD, 1024, FF);
        if (l < LL - 1) {
            red_ln16_kernel<<<NN, 256>>>(part, proj_b + (size_t)l * DD, x,
                ln1_g + (l + 1) * DD, ln1_b + (l + 1) * DD, ln16,
                gate_w + (size_t)(l + 1) * DD * EE,
                noise_w + (size_t)(l + 1) * DD * EE,
                noise + (size_t)(l + 1) * NN * EE, coef);
        } else {
            red_ln16_kernel<<<NN, 256>>>(part, proj_b + (size_t)l * DD, x,
                lnf_g, lnf_b, ln16,
                nullptr, nullptr, nullptr, nullptr);
        }
    }

    {
        int n4 = VV * DD / 4;
        conv16<<<(n4 + 255) / 256, 256>>>(wte, wteH, n4);
    }
    mma_gemm<0, 1><<<gV, 256, SM1>>>(ln16, wteH, nullptr,
                                     out, nullptr, nullptr, VV, DD, DD);
}